// round 2
// baseline (speedup 1.0000x reference)
#include <cuda_runtime.h>
#include <cstdint>

// ---------------------------------------------------------------------------
// FCOS head: 5 levels, batch 2, C=256, 2 towers (4x conv3x3+GN(32)+ReLU),
// heads: cls(80), bbox(4,relu), ctr(1), dim(3), ori(1), kp(16), depth(1).
// Output layout: [cls | bbox | ctr | dim | ori | kp | depth], each
// [N, TotalPos, c] with levels concatenated along pos.
// ---------------------------------------------------------------------------

#define TP 20267          // total positions per batch item
#define ICH 256
#define KCH 8
#define BN 64

// scratch (2*256*100*152 floats = max level tensor)
__device__ float g_bufA[7782400];
__device__ float g_bufB[7782400];
__device__ float g_mean[64];
__device__ float g_inv[64];
__device__ float g_regw[26 * 256 * 9];
__device__ float g_regb[26];

// per-packed-reg-oc output metadata: section base (elements), channels in
// section, channel index, relu flag.
__constant__ long long c_base[26] = {
    3242720LL, 3242720LL, 3242720LL, 3242720LL,                    // bbox
    3404856LL,                                                     // ctr
    3445390LL, 3445390LL, 3445390LL,                               // dim
    3566992LL,                                                     // ori
    3607526LL, 3607526LL, 3607526LL, 3607526LL, 3607526LL, 3607526LL,
    3607526LL, 3607526LL, 3607526LL, 3607526LL, 3607526LL, 3607526LL,
    3607526LL, 3607526LL, 3607526LL, 3607526LL,                    // kp
    4256070LL};                                                    // depth
__constant__ int c_ctot[26] = {4, 4, 4, 4, 1, 3, 3, 3, 1,
                               16, 16, 16, 16, 16, 16, 16, 16,
                               16, 16, 16, 16, 16, 16, 16, 16, 1};
__constant__ int c_ch[26] = {0, 1, 2, 3, 0, 0, 1, 2, 0,
                             0, 1, 2, 3, 4, 5, 6, 7,
                             8, 9, 10, 11, 12, 13, 14, 15, 0};
__constant__ int c_relu[26] = {1, 1, 1, 1, 0, 0, 0, 0, 0,
                               0, 0, 0, 0, 0, 0, 0, 0,
                               0, 0, 0, 0, 0, 0, 0, 0, 0};

// ---------------------------------------------------------------------------
// Pack reg-head weights/biases into one [26,256,9] conv
// ---------------------------------------------------------------------------
__global__ void pack_reg(const float* __restrict__ bbox_w, const float* __restrict__ bbox_b,
                         const float* __restrict__ ctr_w,  const float* __restrict__ ctr_b,
                         const float* __restrict__ dim_w,  const float* __restrict__ dim_b,
                         const float* __restrict__ ori_w,  const float* __restrict__ ori_b,
                         const float* __restrict__ kp_w,   const float* __restrict__ kp_b,
                         const float* __restrict__ depth_w,const float* __restrict__ depth_b) {
    int idx = blockIdx.x * blockDim.x + threadIdx.x;
    int total = 26 * 2304;
    if (idx < total) {
        int oc = idx / 2304;
        int r = idx % 2304;
        const float* src;
        if (oc < 4)       src = bbox_w + oc * 2304;
        else if (oc == 4) src = ctr_w;
        else if (oc < 8)  src = dim_w + (oc - 5) * 2304;
        else if (oc == 8) src = ori_w;
        else if (oc < 25) src = kp_w + (oc - 9) * 2304;
        else              src = depth_w;
        g_regw[idx] = src[r];
    }
    if (idx < 26) {
        float b;
        if (idx < 4)       b = bbox_b[idx];
        else if (idx == 4) b = ctr_b[0];
        else if (idx < 8)  b = dim_b[idx - 5];
        else if (idx == 8) b = ori_b[0];
        else if (idx < 25) b = kp_b[idx - 9];
        else               b = depth_b[0];
        g_regb[idx] = b;
    }
}

// ---------------------------------------------------------------------------
// Tower conv: 3x3 SAME, IC=OC=256, tile 64 oc x 64 cols of one output row.
// grid: (ceil(W/64), H, N*4), block 256.
// ---------------------------------------------------------------------------
__global__ __launch_bounds__(256) void conv_tower(
    const float* __restrict__ x, const float* __restrict__ w,
    const float* __restrict__ bias, float* __restrict__ y, int H, int W) {
    __shared__ __align__(16) float sw[64][KCH][12];
    __shared__ __align__(16) float sx[KCH][3][BN + 4];

    int n = blockIdx.z >> 2;
    int oc0 = (blockIdx.z & 3) * 64;
    int y0 = blockIdx.y;
    int x0 = blockIdx.x * BN;
    int tid = threadIdx.x;
    int ocq = tid >> 4;
    int colq = tid & 15;

    float acc[4][4] = {};

    for (int ic0 = 0; ic0 < ICH; ic0 += KCH) {
        for (int idx = tid; idx < 64 * KCH * 9; idx += 256) {
            int oc = idx / (KCH * 9);
            int r = idx % (KCH * 9);
            int kc = r / 9, t = r % 9;
            sw[oc][kc][t] = w[((oc0 + oc) * ICH + ic0 + kc) * 9 + t];
        }
        for (int idx = tid; idx < KCH * 3 * (BN + 2); idx += 256) {
            int kc = idx / (3 * (BN + 2));
            int r = idx % (3 * (BN + 2));
            int ry = r / (BN + 2), cx = r % (BN + 2);
            int gy = y0 - 1 + ry, gx = x0 - 1 + cx;
            float v = 0.f;
            if (gy >= 0 && gy < H && gx >= 0 && gx < W)
                v = x[((size_t)(n * ICH + ic0 + kc) * H + gy) * W + gx];
            sx[kc][ry][cx] = v;
        }
        __syncthreads();

#pragma unroll
        for (int kc = 0; kc < KCH; kc++) {
            float wr[4][9];
#pragma unroll
            for (int i = 0; i < 4; i++) {
                float4 a = *(const float4*)&sw[ocq * 4 + i][kc][0];
                float4 b = *(const float4*)&sw[ocq * 4 + i][kc][4];
                wr[i][0] = a.x; wr[i][1] = a.y; wr[i][2] = a.z; wr[i][3] = a.w;
                wr[i][4] = b.x; wr[i][5] = b.y; wr[i][6] = b.z; wr[i][7] = b.w;
                wr[i][8] = sw[ocq * 4 + i][kc][8];
            }
#pragma unroll
            for (int ky = 0; ky < 3; ky++) {
                float xr[6];
                float4 a = *(const float4*)&sx[kc][ky][colq * 4];
                xr[0] = a.x; xr[1] = a.y; xr[2] = a.z; xr[3] = a.w;
                xr[4] = sx[kc][ky][colq * 4 + 4];
                xr[5] = sx[kc][ky][colq * 4 + 5];
#pragma unroll
                for (int kx = 0; kx < 3; kx++)
#pragma unroll
                    for (int i = 0; i < 4; i++)
#pragma unroll
                        for (int j = 0; j < 4; j++)
                            acc[i][j] += wr[i][ky * 3 + kx] * xr[j + kx];
            }
        }
        __syncthreads();
    }

#pragma unroll
    for (int i = 0; i < 4; i++) {
        int oc = oc0 + ocq * 4 + i;
        float b = bias[oc];
#pragma unroll
        for (int j = 0; j < 4; j++) {
            int gx = x0 + colq * 4 + j;
            if (gx < W)
                y[((size_t)(n * ICH + oc) * H + y0) * W + gx] = acc[i][j] + b;
        }
    }
}

// ---------------------------------------------------------------------------
// GroupNorm stats: one block per (n, group). groups=32, 8 ch/group.
// ---------------------------------------------------------------------------
__global__ void gn_reduce(const float* __restrict__ x, int HW) {
    int ng = blockIdx.x;
    int n = ng >> 5, g = ng & 31;
    const float* base = x + (size_t)(n * 256 + g * 8) * HW;
    int M = 8 * HW;
    float s = 0.f, sq = 0.f;
    for (int i = threadIdx.x; i < M; i += blockDim.x) {
        float v = base[i];
        s += v;
        sq += v * v;
    }
    __shared__ float ss[256], ssq[256];
    int tid = threadIdx.x;
    ss[tid] = s; ssq[tid] = sq;
    __syncthreads();
    for (int off = 128; off > 0; off >>= 1) {
        if (tid < off) { ss[tid] += ss[tid + off]; ssq[tid] += ssq[tid + off]; }
        __syncthreads();
    }
    if (tid == 0) {
        float mu = ss[0] / M;
        float var = ssq[0] / M - mu * mu;
        g_mean[ng] = mu;
        g_inv[ng] = rsqrtf(var + 1e-5f);
    }
}

__global__ void gn_apply(float* __restrict__ x, const float* __restrict__ gamma,
                         const float* __restrict__ beta, int HW, int total) {
    int i = blockIdx.x * blockDim.x + threadIdx.x;
    if (i >= total) return;
    int c = (i / HW) & 255;
    int n = i / (HW * 256);
    int ng = n * 32 + (c >> 3);
    float v = (x[i] - g_mean[ng]) * g_inv[ng] * gamma[c] + beta[c];
    x[i] = fmaxf(v, 0.f);
}

// ---------------------------------------------------------------------------
// Head conv: 3x3 SAME, IC=256, OC<=96, tile 32 oc x 64 cols. Writes directly
// into d_out. mode 0 = cls (OC=80), mode 1 = packed reg (OC=26).
// grid: (ceil(W/64), H, N*ceil(OC/32)), block 256.
// ---------------------------------------------------------------------------
__global__ __launch_bounds__(256) void conv_head(
    const float* __restrict__ x, const float* __restrict__ w,
    const float* __restrict__ bias, float* __restrict__ out,
    int H, int W, int OC, int levelBase, int mode) {
    __shared__ __align__(16) float sw[32][KCH][12];
    __shared__ __align__(16) float sx[KCH][3][BN + 4];

    int ocBlocks = (OC + 31) >> 5;
    int n = blockIdx.z / ocBlocks;
    int oc0 = (blockIdx.z % ocBlocks) * 32;
    int y0 = blockIdx.y;
    int x0 = blockIdx.x * BN;
    int tid = threadIdx.x;
    int ocq = tid >> 4;
    int colq = tid & 15;

    float acc[2][4] = {};

    for (int ic0 = 0; ic0 < ICH; ic0 += KCH) {
        for (int idx = tid; idx < 32 * KCH * 9; idx += 256) {
            int oc = idx / (KCH * 9);
            int r = idx % (KCH * 9);
            int kc = r / 9, t = r % 9;
            sw[oc][kc][t] = (oc0 + oc < OC)
                                ? w[((oc0 + oc) * ICH + ic0 + kc) * 9 + t]
                                : 0.f;
        }
        for (int idx = tid; idx < KCH * 3 * (BN + 2); idx += 256) {
            int kc = idx / (3 * (BN + 2));
            int r = idx % (3 * (BN + 2));
            int ry = r / (BN + 2), cx = r % (BN + 2);
            int gy = y0 - 1 + ry, gx = x0 - 1 + cx;
            float v = 0.f;
            if (gy >= 0 && gy < H && gx >= 0 && gx < W)
                v = x[((size_t)(n * ICH + ic0 + kc) * H + gy) * W + gx];
            sx[kc][ry][cx] = v;
        }
        __syncthreads();

#pragma unroll
        for (int kc = 0; kc < KCH; kc++) {
            float wr[2][9];
#pragma unroll
            for (int i = 0; i < 2; i++) {
                float4 a = *(const float4*)&sw[ocq * 2 + i][kc][0];
                float4 b = *(const float4*)&sw[ocq * 2 + i][kc][4];
                wr[i][0] = a.x; wr[i][1] = a.y; wr[i][2] = a.z; wr[i][3] = a.w;
                wr[i][4] = b.x; wr[i][5] = b.y; wr[i][6] = b.z; wr[i][7] = b.w;
                wr[i][8] = sw[ocq * 2 + i][kc][8];
            }
#pragma unroll
            for (int ky = 0; ky < 3; ky++) {
                float xr[6];
                float4 a = *(const float4*)&sx[kc][ky][colq * 4];
                xr[0] = a.x; xr[1] = a.y; xr[2] = a.z; xr[3] = a.w;
                xr[4] = sx[kc][ky][colq * 4 + 4];
                xr[5] = sx[kc][ky][colq * 4 + 5];
#pragma unroll
                for (int kx = 0; kx < 3; kx++)
#pragma unroll
                    for (int i = 0; i < 2; i++)
#pragma unroll
                        for (int j = 0; j < 4; j++)
                            acc[i][j] += wr[i][ky * 3 + kx] * xr[j + kx];
            }
        }
        __syncthreads();
    }

#pragma unroll
    for (int i = 0; i < 2; i++) {
        int oc = oc0 + ocq * 2 + i;
        if (oc >= OC) continue;
        float b = bias[oc];
#pragma unroll
        for (int j = 0; j < 4; j++) {
            int gx = x0 + colq * 4 + j;
            if (gx >= W) continue;
            float v = acc[i][j] + b;
            long long unit = (long long)n * TP + levelBase + (long long)y0 * W + gx;
            long long addr;
            if (mode == 0) {
                addr = unit * 80 + oc;          // cls section at base 0
            } else {
                addr = c_base[oc] + unit * c_ctot[oc] + c_ch[oc];
                if (c_relu[oc]) v = fmaxf(v, 0.f);
            }
            out[addr] = v;
        }
    }
}

// ---------------------------------------------------------------------------
// Host orchestration
// ---------------------------------------------------------------------------
extern "C" void kernel_launch(void* const* d_in, const int* in_sizes, int n_in,
                              void* d_out, int out_size) {
    const float* feats[5];
    for (int i = 0; i < 5; i++) feats[i] = (const float*)d_in[i];
    const float* cls_conv_w = (const float*)d_in[5];
    const float* cls_conv_b = (const float*)d_in[6];
    const float* cls_gn_w = (const float*)d_in[7];
    const float* cls_gn_b = (const float*)d_in[8];
    const float* cls_out_w = (const float*)d_in[9];
    const float* cls_out_b = (const float*)d_in[10];
    const float* reg_conv_w = (const float*)d_in[11];
    const float* reg_conv_b = (const float*)d_in[12];
    const float* reg_gn_w = (const float*)d_in[13];
    const float* reg_gn_b = (const float*)d_in[14];
    float* out = (float*)d_out;

    float *bufA, *bufB, *regw, *regb;
    cudaGetSymbolAddress((void**)&bufA, g_bufA);
    cudaGetSymbolAddress((void**)&bufB, g_bufB);
    cudaGetSymbolAddress((void**)&regw, g_regw);
    cudaGetSymbolAddress((void**)&regb, g_regb);

    pack_reg<<<(26 * 2304 + 255) / 256, 256>>>(
        (const float*)d_in[15], (const float*)d_in[16],   // bbox
        (const float*)d_in[17], (const float*)d_in[18],   // ctr
        (const float*)d_in[19], (const float*)d_in[20],   // dim
        (const float*)d_in[21], (const float*)d_in[22],   // ori
        (const float*)d_in[23], (const float*)d_in[24],   // kp
        (const float*)d_in[25], (const float*)d_in[26]);  // depth

    const int Hs[5] = {100, 50, 25, 13, 7};
    const int Ws[5] = {152, 76, 38, 19, 10};
    const int lvlBase[5] = {0, 15200, 19000, 19950, 20197};

    for (int lvl = 0; lvl < 5; lvl++) {
        int H = Hs[lvl], W = Ws[lvl];
        int HW = H * W;
        int total = 2 * 256 * HW;
        dim3 gConv((W + BN - 1) / BN, H, 2 * 4);
        int gApply = (total + 255) / 256;

        // --- cls tower ---
        const float* cur = feats[lvl];
        float* bufs[2] = {bufA, bufB};
        for (int s = 0; s < 4; s++) {
            float* dst = bufs[s & 1];
            conv_tower<<<gConv, 256>>>(cur, cls_conv_w + (size_t)s * 256 * 256 * 9,
                                       cls_conv_b + s * 256, dst, H, W);
            gn_reduce<<<64, 256>>>(dst, HW);
            gn_apply<<<gApply, 256>>>(dst, cls_gn_w + s * 256, cls_gn_b + s * 256,
                                      HW, total);
            cur = dst;
        }
        {
            dim3 gHead((W + BN - 1) / BN, H, 2 * 3);  // OC=80 -> 3 oc blocks
            conv_head<<<gHead, 256>>>(cur, cls_out_w, cls_out_b, out, H, W, 80,
                                      lvlBase[lvl], 0);
        }

        // --- reg tower ---
        cur = feats[lvl];
        for (int s = 0; s < 4; s++) {
            float* dst = bufs[s & 1];
            conv_tower<<<gConv, 256>>>(cur, reg_conv_w + (size_t)s * 256 * 256 * 9,
                                       reg_conv_b + s * 256, dst, H, W);
            gn_reduce<<<64, 256>>>(dst, HW);
            gn_apply<<<gApply, 256>>>(dst, reg_gn_w + s * 256, reg_gn_b + s * 256,
                                      HW, total);
            cur = dst;
        }
        {
            dim3 gHead((W + BN - 1) / BN, H, 2 * 1);  // OC=26 -> 1 oc block
            conv_head<<<gHead, 256>>>(cur, regw, regb, out, H, W, 26,
                                      lvlBase[lvl], 1);
        }
    }
    (void)in_sizes; (void)n_in; (void)out_size;
}

// round 3
// speedup vs baseline: 2.7314x; 2.7314x over previous
#include <cuda_runtime.h>
#include <cstdint>

// ---------------------------------------------------------------------------
// FCOS head. Towers now run as implicit GEMM on tensor cores (tf32 mma.sync):
// conv3x3 = sum over 9 taps of shifted GEMMs with K=256.
// ---------------------------------------------------------------------------

#define TP 20267          // total positions per batch item
#define ICH 256
#define BN 64
#define KCH 8

// scratch
__device__ float g_bufA[7782400];
__device__ float g_bufB[7782400];
__device__ float g_bufC[7782400];
__device__ float g_mean[64];
__device__ float g_inv[64];
__device__ float g_regw[26 * 256 * 9];
__device__ float g_regb[26];
__device__ float g_wt_cls[4 * 9 * 256 * 256];   // [s][tap][ic][oc]
__device__ float g_wt_reg[4 * 9 * 256 * 256];

// reg-head packed output metadata
__constant__ long long c_base[26] = {
    3242720LL, 3242720LL, 3242720LL, 3242720LL,
    3404856LL,
    3445390LL, 3445390LL, 3445390LL,
    3566992LL,
    3607526LL, 3607526LL, 3607526LL, 3607526LL, 3607526LL, 3607526LL,
    3607526LL, 3607526LL, 3607526LL, 3607526LL, 3607526LL, 3607526LL,
    3607526LL, 3607526LL, 3607526LL, 3607526LL,
    4256070LL};
__constant__ int c_ctot[26] = {4, 4, 4, 4, 1, 3, 3, 3, 1,
                               16, 16, 16, 16, 16, 16, 16, 16,
                               16, 16, 16, 16, 16, 16, 16, 16, 1};
__constant__ int c_ch[26] = {0, 1, 2, 3, 0, 0, 1, 2, 0,
                             0, 1, 2, 3, 4, 5, 6, 7,
                             8, 9, 10, 11, 12, 13, 14, 15, 0};
__constant__ int c_relu[26] = {1, 1, 1, 1, 0, 0, 0, 0, 0,
                               0, 0, 0, 0, 0, 0, 0, 0,
                               0, 0, 0, 0, 0, 0, 0, 0, 0};

__device__ __forceinline__ float tf32r(float v) {
    float o;
    asm("cvt.rna.tf32.f32 %0, %1;" : "=f"(o) : "f"(v));
    return o;
}

__device__ __forceinline__ void cpa4(float* dst, const float* src, int sz) {
    uint32_t d = (uint32_t)__cvta_generic_to_shared(dst);
    asm volatile("cp.async.ca.shared.global [%0], [%1], 4, %2;" ::"r"(d), "l"(src), "r"(sz));
}
__device__ __forceinline__ void cpa16(float* dst, const float* src) {
    uint32_t d = (uint32_t)__cvta_generic_to_shared(dst);
    asm volatile("cp.async.ca.shared.global [%0], [%1], 16;" ::"r"(d), "l"(src));
}

// ---------------------------------------------------------------------------
// Weight transform: w[s][oc][ic][tap] -> wt[s][tap][ic][oc], rounded to tf32.
// ---------------------------------------------------------------------------
__global__ void pack_wt(const float* __restrict__ w, float* __restrict__ wt) {
    int idx = blockIdx.x * blockDim.x + threadIdx.x;   // over 4*9*256*256
    if (idx >= 4 * 9 * 256 * 256) return;
    int oc = idx & 255;
    int ic = (idx >> 8) & 255;
    int tap = (idx >> 16) % 9;
    int s = idx / (9 * 256 * 256);
    wt[idx] = tf32r(w[(((size_t)(s * 256 + oc) * 256 + ic) * 9) + tap]);
}

// round feats to tf32 grid
__global__ void round_feats(const float* __restrict__ x, float* __restrict__ y, int total) {
    int i = blockIdx.x * blockDim.x + threadIdx.x;
    if (i < total) y[i] = tf32r(x[i]);
}

// ---------------------------------------------------------------------------
// Pack reg-head weights/biases into one [26,256,9] conv
// ---------------------------------------------------------------------------
__global__ void pack_reg(const float* __restrict__ bbox_w, const float* __restrict__ bbox_b,
                         const float* __restrict__ ctr_w,  const float* __restrict__ ctr_b,
                         const float* __restrict__ dim_w,  const float* __restrict__ dim_b,
                         const float* __restrict__ ori_w,  const float* __restrict__ ori_b,
                         const float* __restrict__ kp_w,   const float* __restrict__ kp_b,
                         const float* __restrict__ depth_w,const float* __restrict__ depth_b) {
    int idx = blockIdx.x * blockDim.x + threadIdx.x;
    int total = 26 * 2304;
    if (idx < total) {
        int oc = idx / 2304;
        int r = idx % 2304;
        const float* src;
        if (oc < 4)       src = bbox_w + oc * 2304;
        else if (oc == 4) src = ctr_w;
        else if (oc < 8)  src = dim_w + (oc - 5) * 2304;
        else if (oc == 8) src = ori_w;
        else if (oc < 25) src = kp_w + (oc - 9) * 2304;
        else              src = depth_w;
        g_regw[idx] = src[r];
    }
    if (idx < 26) {
        float b;
        if (idx < 4)       b = bbox_b[idx];
        else if (idx == 4) b = ctr_b[0];
        else if (idx < 8)  b = dim_b[idx - 5];
        else if (idx == 8) b = ori_b[0];
        else if (idx < 25) b = kp_b[idx - 9];
        else               b = depth_b[0];
        g_regb[idx] = b;
    }
}

// ---------------------------------------------------------------------------
// Tower conv as implicit GEMM (tf32 mma.sync m16n8k8).
// C[M=128 positions, N=128 oc] over K = 9 taps * 256 ic, staged 16 ic at a
// time, double-buffered cp.async. grid: (Mtiles, 2), block 256 (8 warps 2x4).
// ---------------------------------------------------------------------------
__global__ __launch_bounds__(256, 2) void gemm_conv(
    const float* __restrict__ x, const float* __restrict__ wt,
    const float* __restrict__ bias, float* __restrict__ y,
    int H, int W, int HW, int P) {
    __shared__ float sA[2][16][136];
    __shared__ float sB[2][16][136];
    __shared__ int soff[128], ssy[128], ssx[128];

    int tid = threadIdx.x;
    int p0 = blockIdx.x * 128;
    int oc0 = blockIdx.y * 128;

    if (tid < 128) {
        int p = p0 + tid;
        if (p < P) {
            int n = p / HW;
            int r = p - n * HW;
            int yy = r / W;
            int xx = r - yy * W;
            soff[tid] = (n * 256) * HW + yy * W + xx;
            ssy[tid] = yy;
            ssx[tid] = xx;
        } else {
            soff[tid] = 0;
            ssy[tid] = -100000;
            ssx[tid] = -100000;
        }
    }
    __syncthreads();

    int am = tid & 127, ahi = tid >> 7;
    int a_off = soff[am], a_y = ssy[am], a_x = ssx[am];

    int warp = tid >> 5, lane = tid & 31, g = lane >> 2, t4 = lane & 3;
    int mwarp = (warp >> 2) * 64, nwarp = (warp & 3) * 32;

    float acc[4][4][4];
#pragma unroll
    for (int i = 0; i < 4; i++)
#pragma unroll
        for (int j = 0; j < 4; j++)
#pragma unroll
            for (int q = 0; q < 4; q++) acc[i][j][q] = 0.f;

    const int STAGES = 9 * 16;

    auto prefetch = [&](int s, int buf) {
        int tap = s >> 4;
        int ic0 = (s & 15) * 16;
        int dy = tap / 3 - 1, dx = tap % 3 - 1;
        // A: 16k x 128m, this thread: column am, rows ahi,ahi+2,...
        int yy = a_y + dy, xx = a_x + dx;
        bool valid = ((unsigned)yy < (unsigned)H) && ((unsigned)xx < (unsigned)W);
        int sz = valid ? 4 : 0;
        const float* gA = x + (valid ? (a_off + ic0 * HW + dy * W + dx) : 0);
#pragma unroll
        for (int it = 0; it < 8; it++) {
            int kk = it * 2 + ahi;
            cpa4(&sA[buf][kk][am], gA + (size_t)kk * HW, sz);
        }
        // B: 16k x 128n, fully coalesced 16B chunks
        const float* gB = wt + (size_t)(tap * 256 + ic0) * 256 + oc0;
#pragma unroll
        for (int j = 0; j < 2; j++) {
            int c = tid + j * 256;
            int row = c >> 5;
            int col = (c & 31) * 4;
            cpa16(&sB[buf][row][col], gB + row * 256 + col);
        }
        asm volatile("cp.async.commit_group;");
    };

    prefetch(0, 0);

    for (int s = 0; s < STAGES; s++) {
        int buf = s & 1;
        if (s + 1 < STAGES) {
            prefetch(s + 1, buf ^ 1);
            asm volatile("cp.async.wait_group 1;");
        } else {
            asm volatile("cp.async.wait_group 0;");
        }
        __syncthreads();

#pragma unroll
        for (int st = 0; st < 2; st++) {
            int kb = st * 8;
            uint32_t A[4][4], Bf[4][2];
#pragma unroll
            for (int mt = 0; mt < 4; mt++) {
                int r0 = mwarp + mt * 16 + g;
                A[mt][0] = __float_as_uint(sA[buf][kb + t4][r0]);
                A[mt][1] = __float_as_uint(sA[buf][kb + t4][r0 + 8]);
                A[mt][2] = __float_as_uint(sA[buf][kb + t4 + 4][r0]);
                A[mt][3] = __float_as_uint(sA[buf][kb + t4 + 4][r0 + 8]);
            }
#pragma unroll
            for (int nt = 0; nt < 4; nt++) {
                int cc = nwarp + nt * 8 + g;
                Bf[nt][0] = __float_as_uint(sB[buf][kb + t4][cc]);
                Bf[nt][1] = __float_as_uint(sB[buf][kb + t4 + 4][cc]);
            }
#pragma unroll
            for (int mt = 0; mt < 4; mt++)
#pragma unroll
                for (int nt = 0; nt < 4; nt++) {
                    asm volatile(
                        "mma.sync.aligned.m16n8k8.row.col.f32.tf32.tf32.f32 "
                        "{%0,%1,%2,%3}, {%4,%5,%6,%7}, {%8,%9}, {%0,%1,%2,%3};"
                        : "+f"(acc[mt][nt][0]), "+f"(acc[mt][nt][1]),
                          "+f"(acc[mt][nt][2]), "+f"(acc[mt][nt][3])
                        : "r"(A[mt][0]), "r"(A[mt][1]), "r"(A[mt][2]), "r"(A[mt][3]),
                          "r"(Bf[nt][0]), "r"(Bf[nt][1]));
                }
        }
        __syncthreads();
    }

    // epilogue: C[m][n] -> y[n_img][oc][yy][xx] + bias
#pragma unroll
    for (int nt = 0; nt < 4; nt++) {
        int oc = oc0 + nwarp + nt * 8 + 2 * t4;
        float b0 = bias[oc];
        float b1 = bias[oc + 1];
#pragma unroll
        for (int mt = 0; mt < 4; mt++) {
            int r0 = mwarp + mt * 16 + g;
            int r1 = r0 + 8;
            if (p0 + r0 < P) {
                int base = soff[r0];
                y[(size_t)base + (size_t)oc * HW] = acc[mt][nt][0] + b0;
                y[(size_t)base + (size_t)(oc + 1) * HW] = acc[mt][nt][1] + b1;
            }
            if (p0 + r1 < P) {
                int base = soff[r1];
                y[(size_t)base + (size_t)oc * HW] = acc[mt][nt][2] + b0;
                y[(size_t)base + (size_t)(oc + 1) * HW] = acc[mt][nt][3] + b1;
            }
        }
    }
}

// ---------------------------------------------------------------------------
// GroupNorm
// ---------------------------------------------------------------------------
__global__ void gn_reduce(const float* __restrict__ x, int HW) {
    int ng = blockIdx.x;
    int n = ng >> 5, gr = ng & 31;
    const float* base = x + (size_t)(n * 256 + gr * 8) * HW;
    int M = 8 * HW;
    float s = 0.f, sq = 0.f;
    for (int i = threadIdx.x; i < M; i += blockDim.x) {
        float v = base[i];
        s += v;
        sq += v * v;
    }
    __shared__ float ss[256], ssq[256];
    int tid = threadIdx.x;
    ss[tid] = s; ssq[tid] = sq;
    __syncthreads();
    for (int off = 128; off > 0; off >>= 1) {
        if (tid < off) { ss[tid] += ss[tid + off]; ssq[tid] += ssq[tid + off]; }
        __syncthreads();
    }
    if (tid == 0) {
        float mu = ss[0] / M;
        float var = ssq[0] / M - mu * mu;
        g_mean[ng] = mu;
        g_inv[ng] = rsqrtf(var + 1e-5f);
    }
}

__global__ void gn_apply(float* __restrict__ x, const float* __restrict__ gamma,
                         const float* __restrict__ beta, int HW, int total) {
    int i = blockIdx.x * blockDim.x + threadIdx.x;
    if (i >= total) return;
    int c = (i / HW) & 255;
    int n = i / (HW * 256);
    int ng = n * 32 + (c >> 3);
    float v = (x[i] - g_mean[ng]) * g_inv[ng] * gamma[c] + beta[c];
    x[i] = tf32r(fmaxf(v, 0.f));   // pre-round for next tf32 GEMM
}

// ---------------------------------------------------------------------------
// Head conv (fp32 direct): mode 0 = cls (OC=80), mode 1 = packed reg (OC=26).
// ---------------------------------------------------------------------------
__global__ __launch_bounds__(256) void conv_head(
    const float* __restrict__ x, const float* __restrict__ w,
    const float* __restrict__ bias, float* __restrict__ out,
    int H, int W, int OC, int levelBase, int mode) {
    __shared__ __align__(16) float sw[32][KCH][12];
    __shared__ __align__(16) float sx[KCH][3][BN + 4];

    int ocBlocks = (OC + 31) >> 5;
    int n = blockIdx.z / ocBlocks;
    int oc0 = (blockIdx.z % ocBlocks) * 32;
    int y0 = blockIdx.y;
    int x0 = blockIdx.x * BN;
    int tid = threadIdx.x;
    int ocq = tid >> 4;
    int colq = tid & 15;

    float acc[2][4] = {};

    for (int ic0 = 0; ic0 < ICH; ic0 += KCH) {
        for (int idx = tid; idx < 32 * KCH * 9; idx += 256) {
            int oc = idx / (KCH * 9);
            int r = idx % (KCH * 9);
            int kc = r / 9, t = r % 9;
            sw[oc][kc][t] = (oc0 + oc < OC)
                                ? w[((oc0 + oc) * ICH + ic0 + kc) * 9 + t]
                                : 0.f;
        }
        for (int idx = tid; idx < KCH * 3 * (BN + 2); idx += 256) {
            int kc = idx / (3 * (BN + 2));
            int r = idx % (3 * (BN + 2));
            int ry = r / (BN + 2), cx = r % (BN + 2);
            int gy = y0 - 1 + ry, gx = x0 - 1 + cx;
            float v = 0.f;
            if (gy >= 0 && gy < H && gx >= 0 && gx < W)
                v = x[((size_t)(n * ICH + ic0 + kc) * H + gy) * W + gx];
            sx[kc][ry][cx] = v;
        }
        __syncthreads();

#pragma unroll
        for (int kc = 0; kc < KCH; kc++) {
            float wr[2][9];
#pragma unroll
            for (int i = 0; i < 2; i++) {
                float4 a = *(const float4*)&sw[ocq * 2 + i][kc][0];
                float4 b = *(const float4*)&sw[ocq * 2 + i][kc][4];
                wr[i][0] = a.x; wr[i][1] = a.y; wr[i][2] = a.z; wr[i][3] = a.w;
                wr[i][4] = b.x; wr[i][5] = b.y; wr[i][6] = b.z; wr[i][7] = b.w;
                wr[i][8] = sw[ocq * 2 + i][kc][8];
            }
#pragma unroll
            for (int ky = 0; ky < 3; ky++) {
                float xr[6];
                float4 a = *(const float4*)&sx[kc][ky][colq * 4];
                xr[0] = a.x; xr[1] = a.y; xr[2] = a.z; xr[3] = a.w;
                xr[4] = sx[kc][ky][colq * 4 + 4];
                xr[5] = sx[kc][ky][colq * 4 + 5];
#pragma unroll
                for (int kx = 0; kx < 3; kx++)
#pragma unroll
                    for (int i = 0; i < 2; i++)
#pragma unroll
                        for (int j = 0; j < 4; j++)
                            acc[i][j] += wr[i][ky * 3 + kx] * xr[j + kx];
            }
        }
        __syncthreads();
    }

#pragma unroll
    for (int i = 0; i < 2; i++) {
        int oc = oc0 + ocq * 2 + i;
        if (oc >= OC) continue;
        float b = bias[oc];
#pragma unroll
        for (int j = 0; j < 4; j++) {
            int gx = x0 + colq * 4 + j;
            if (gx >= W) continue;
            float v = acc[i][j] + b;
            long long unit = (long long)n * TP + levelBase + (long long)y0 * W + gx;
            long long addr;
            if (mode == 0) {
                addr = unit * 80 + oc;
            } else {
                addr = c_base[oc] + unit * c_ctot[oc] + c_ch[oc];
                if (c_relu[oc]) v = fmaxf(v, 0.f);
            }
            out[addr] = v;
        }
    }
}

// ---------------------------------------------------------------------------
// Host orchestration
// ---------------------------------------------------------------------------
extern "C" void kernel_launch(void* const* d_in, const int* in_sizes, int n_in,
                              void* d_out, int out_size) {
    const float* feats[5];
    for (int i = 0; i < 5; i++) feats[i] = (const float*)d_in[i];
    const float* cls_conv_w = (const float*)d_in[5];
    const float* cls_conv_b = (const float*)d_in[6];
    const float* cls_gn_w = (const float*)d_in[7];
    const float* cls_gn_b = (const float*)d_in[8];
    const float* cls_out_w = (const float*)d_in[9];
    const float* cls_out_b = (const float*)d_in[10];
    const float* reg_conv_w = (const float*)d_in[11];
    const float* reg_conv_b = (const float*)d_in[12];
    const float* reg_gn_w = (const float*)d_in[13];
    const float* reg_gn_b = (const float*)d_in[14];
    float* out = (float*)d_out;

    float *bufA, *bufB, *bufC, *regw, *regb, *wtc, *wtr;
    cudaGetSymbolAddress((void**)&bufA, g_bufA);
    cudaGetSymbolAddress((void**)&bufB, g_bufB);
    cudaGetSymbolAddress((void**)&bufC, g_bufC);
    cudaGetSymbolAddress((void**)&regw, g_regw);
    cudaGetSymbolAddress((void**)&regb, g_regb);
    cudaGetSymbolAddress((void**)&wtc, g_wt_cls);
    cudaGetSymbolAddress((void**)&wtr, g_wt_reg);

    pack_reg<<<(26 * 2304 + 255) / 256, 256>>>(
        (const float*)d_in[15], (const float*)d_in[16],
        (const float*)d_in[17], (const float*)d_in[18],
        (const float*)d_in[19], (const float*)d_in[20],
        (const float*)d_in[21], (const float*)d_in[22],
        (const float*)d_in[23], (const float*)d_in[24],
        (const float*)d_in[25], (const float*)d_in[26]);

    int wtN = 4 * 9 * 256 * 256;
    pack_wt<<<(wtN + 255) / 256, 256>>>(cls_conv_w, wtc);
    pack_wt<<<(wtN + 255) / 256, 256>>>(reg_conv_w, wtr);

    const int Hs[5] = {100, 50, 25, 13, 7};
    const int Ws[5] = {152, 76, 38, 19, 10};
    const int lvlBase[5] = {0, 15200, 19000, 19950, 20197};

    for (int lvl = 0; lvl < 5; lvl++) {
        int H = Hs[lvl], W = Ws[lvl];
        int HW = H * W;
        int total = 2 * 256 * HW;
        int P = 2 * HW;
        int Mtiles = (P + 127) / 128;
        dim3 gGemm(Mtiles, 2);
        int gApply = (total + 255) / 256;

        round_feats<<<(total + 255) / 256, 256>>>(feats[lvl], bufC, total);

        float* bufs[2] = {bufA, bufB};

        // --- cls tower ---
        const float* cur = bufC;
        for (int s = 0; s < 4; s++) {
            float* dst = bufs[s & 1];
            gemm_conv<<<gGemm, 256>>>(cur, wtc + (size_t)s * 589824,
                                      cls_conv_b + s * 256, dst, H, W, HW, P);
            gn_reduce<<<64, 256>>>(dst, HW);
            gn_apply<<<gApply, 256>>>(dst, cls_gn_w + s * 256, cls_gn_b + s * 256,
                                      HW, total);
            cur = dst;
        }
        {
            dim3 gHead((W + BN - 1) / BN, H, 2 * 3);
            conv_head<<<gHead, 256>>>(cur, cls_out_w, cls_out_b, out, H, W, 80,
                                      lvlBase[lvl], 0);
        }

        // --- reg tower ---
        cur = bufC;
        for (int s = 0; s < 4; s++) {
            float* dst = bufs[s & 1];
            gemm_conv<<<gGemm, 256>>>(cur, wtr + (size_t)s * 589824,
                                      reg_conv_b + s * 256, dst, H, W, HW, P);
            gn_reduce<<<64, 256>>>(dst, HW);
            gn_apply<<<gApply, 256>>>(dst, reg_gn_w + s * 256, reg_gn_b + s * 256,
                                      HW, total);
            cur = dst;
        }
        {
            dim3 gHead((W + BN - 1) / BN, H, 2 * 1);
            conv_head<<<gHead, 256>>>(cur, regw, regb, out, H, W, 26,
                                      lvlBase[lvl], 1);
        }
    }
    (void)in_sizes; (void)n_in; (void)out_size;
}

// round 5
// speedup vs baseline: 4.5186x; 1.6543x over previous
#include <cuda_runtime.h>
#include <cuda_fp16.h>
#include <cstdint>

// ---------------------------------------------------------------------------
// FCOS head, all convs on fp16 mma.sync (m16n8k16, fp32 accum).
// Activations NHWC half; conv3x3 = 9 shifted GEMM taps.
// ---------------------------------------------------------------------------

#define TP 20267
#define PAD 20    // smem row pitch in uint32 words (16 data + 4 pad)

__device__ __half g_xh[7782400];
__device__ __half g_actA[7782400];
__device__ __half g_actB[7782400];
__device__ float  g_y[7782400];
__device__ float  g_mean[64];
__device__ float  g_inv[64];
__device__ float  g_regw[26 * 256 * 9];
__device__ float  g_regb[26];
__device__ __half g_wt_cls[4 * 9 * 256 * 256];   // [s][tap][oc][ic] half
__device__ __half g_wt_reg[4 * 9 * 256 * 256];
__device__ __half g_wtc_out[2 * 9 * 128 * 256];  // [part][tap][ocpad][ic]
__device__ __half g_wtr_out[2 * 9 * 128 * 256];

__constant__ long long c_base[26] = {
    3242720LL, 3242720LL, 3242720LL, 3242720LL,
    3404856LL,
    3445390LL, 3445390LL, 3445390LL,
    3566992LL,
    3607526LL, 3607526LL, 3607526LL, 3607526LL, 3607526LL, 3607526LL,
    3607526LL, 3607526LL, 3607526LL, 3607526LL, 3607526LL, 3607526LL,
    3607526LL, 3607526LL, 3607526LL, 3607526LL,
    4256070LL};
__constant__ int c_ctot[26] = {4, 4, 4, 4, 1, 3, 3, 3, 1,
                               16, 16, 16, 16, 16, 16, 16, 16,
                               16, 16, 16, 16, 16, 16, 16, 16, 1};
__constant__ int c_ch[26] = {0, 1, 2, 3, 0, 0, 1, 2, 0,
                             0, 1, 2, 3, 4, 5, 6, 7,
                             8, 9, 10, 11, 12, 13, 14, 15, 0};
__constant__ int c_relu[26] = {1, 1, 1, 1, 0, 0, 0, 0, 0,
                               0, 0, 0, 0, 0, 0, 0, 0,
                               0, 0, 0, 0, 0, 0, 0, 0, 0};

__device__ __forceinline__ void cpa16p(uint32_t d, const void* s, int sz) {
    asm volatile("cp.async.cg.shared.global [%0], [%1], 16, %2;" ::"r"(d), "l"(s), "r"(sz));
}

// ---------------------------------------------------------------------------
// NCHW fp32 -> NHWC half (tile transpose)
// ---------------------------------------------------------------------------
__global__ void to_nhwc_half(const float* __restrict__ src, __half* __restrict__ dst,
                             int HW) {
    __shared__ float t[32][33];
    int n = blockIdx.z;
    int p0 = blockIdx.x * 32, c0 = blockIdx.y * 32;
    int tx = threadIdx.x, ty = threadIdx.y;
    int p = p0 + tx, c = c0 + ty;
    if (p < HW) t[ty][tx] = src[((size_t)(n * 256 + c)) * HW + p];
    __syncthreads();
    int p2 = p0 + ty, c2 = c0 + tx;
    if (p2 < HW) dst[((size_t)(n * HW + p2)) * 256 + c2] = __float2half_rn(t[tx][ty]);
}

// ---------------------------------------------------------------------------
// Weight packs
// ---------------------------------------------------------------------------
__global__ void pack_wt(const float* __restrict__ w, __half* __restrict__ wt) {
    int idx = blockIdx.x * blockDim.x + threadIdx.x;
    if (idx >= 4 * 9 * 256 * 256) return;
    int ic = idx & 255;
    int oc = (idx >> 8) & 255;
    int tap = (idx >> 16) % 9;
    int s = idx / 589824;
    wt[idx] = __float2half_rn(w[(((size_t)(s * 256 + oc) * 256 + ic) * 9) + tap]);
}

// src [OC][256][9] fp32 -> dst [2 part][9][128][256] half (hi / lo split)
__global__ void pack_headw(const float* __restrict__ src, __half* __restrict__ dst,
                           int OC) {
    int idx = blockIdx.x * blockDim.x + threadIdx.x;
    if (idx >= 2 * 9 * 128 * 256) return;
    int ic = idx & 255;
    int oc = (idx >> 8) & 127;
    int tap = (idx >> 15) % 9;
    int part = idx / (9 * 128 * 256);
    float v = 0.f;
    if (oc < OC) v = src[((size_t)oc * 256 + ic) * 9 + tap];
    __half hi = __float2half_rn(v);
    dst[idx] = (part == 0) ? hi : __float2half_rn(v - __half2float(hi));
}

__global__ void pack_reg(const float* __restrict__ bbox_w, const float* __restrict__ bbox_b,
                         const float* __restrict__ ctr_w,  const float* __restrict__ ctr_b,
                         const float* __restrict__ dim_w,  const float* __restrict__ dim_b,
                         const float* __restrict__ ori_w,  const float* __restrict__ ori_b,
                         const float* __restrict__ kp_w,   const float* __restrict__ kp_b,
                         const float* __restrict__ depth_w,const float* __restrict__ depth_b) {
    int idx = blockIdx.x * blockDim.x + threadIdx.x;
    int total = 26 * 2304;
    if (idx < total) {
        int oc = idx / 2304;
        int r = idx % 2304;
        const float* src;
        if (oc < 4)       src = bbox_w + oc * 2304;
        else if (oc == 4) src = ctr_w;
        else if (oc < 8)  src = dim_w + (oc - 5) * 2304;
        else if (oc == 8) src = ori_w;
        else if (oc < 25) src = kp_w + (oc - 9) * 2304;
        else              src = depth_w;
        g_regw[idx] = src[r];
    }
    if (idx < 26) {
        float b;
        if (idx < 4)       b = bbox_b[idx];
        else if (idx == 4) b = ctr_b[0];
        else if (idx < 8)  b = dim_b[idx - 5];
        else if (idx == 8) b = ori_b[0];
        else if (idx < 25) b = kp_b[idx - 9];
        else               b = depth_b[0];
        g_regb[idx] = b;
    }
}

// ---------------------------------------------------------------------------
// fp16 implicit-GEMM conv. M=128 positions x N=128 oc, K staged 32 halves.
// mode 0: tower (write fp32 NHWC y). mode 1: cls head -> d_out.
// mode 2: packed reg head -> d_out.
// grid: (Mtiles, Ntiles). block 256.
// ---------------------------------------------------------------------------
__global__ __launch_bounds__(256, 2) void gemm16(
    const __half* __restrict__ x, const __half* __restrict__ wt,
    const float* __restrict__ bias, float* __restrict__ out,
    int H, int W, int HW, int P, int OCROWS, int NSTAGES, int mode,
    int levelBase, int OC) {
    __shared__ uint32_t sbuf[2][2][128 * PAD];
    __shared__ int sbase[128], syy[128], sxx[128], sn[128];

    int tid = threadIdx.x;
    int p0 = blockIdx.x * 128;
    int oc0 = blockIdx.y * 128;

    if (tid < 128) {
        int p = p0 + tid;
        if (p < P) {
            int n = p >= HW ? 1 : 0;
            int rr = p - n * HW;
            int yy = rr / W;
            int xx = rr - yy * W;
            sbase[tid] = p * 256;
            syy[tid] = yy;
            sxx[tid] = xx;
            sn[tid] = n;
        } else {
            sbase[tid] = 0;
            syy[tid] = -100000;
            sxx[tid] = -100000;
            sn[tid] = 0;
        }
    }
    __syncthreads();

    int warp = tid >> 5, lane = tid & 31, g = lane >> 2, t4 = lane & 3;
    int mwarp = (warp >> 2) * 64, nwarp = (warp & 3) * 32;

    float acc[4][4][4];
#pragma unroll
    for (int i = 0; i < 4; i++)
#pragma unroll
        for (int j = 0; j < 4; j++)
#pragma unroll
            for (int q = 0; q < 4; q++) acc[i][j][q] = 0.f;

    int m0 = tid >> 2, cw0 = tid & 3;
    uint32_t dstA0 = (uint32_t)__cvta_generic_to_shared(&sbuf[0][0][0]);
    uint32_t dstB0 = (uint32_t)__cvta_generic_to_shared(&sbuf[0][1][0]);
    const uint32_t bufstride = 2 * 128 * PAD * 4;

    auto load_chunk = [&](int c, int b) {
        int cc = c % 72;
        int part = c / 72;
        int tap = cc >> 3;
        int icc = (cc & 7) << 5;
        int ty = tap / 3;
        int dy = ty - 1, dx = tap - ty * 3 - 1;
        int shift = (dy * W + dx) * 256;
        const __half* wsrc = wt + (size_t)part * (9 * 128 * 256);
#pragma unroll
        for (int j = 0; j < 2; j++) {
            int m = m0 + j * 64;
            int gy = syy[m] + dy, gx = sxx[m] + dx;
            bool v = ((unsigned)gy < (unsigned)H) && ((unsigned)gx < (unsigned)W);
            const __half* src = x + (v ? (sbase[m] + shift + icc + cw0 * 8) : 0);
            cpa16p(dstA0 + b * bufstride + (m * PAD + cw0 * 4) * 4, src, v ? 16 : 0);
        }
#pragma unroll
        for (int j = 0; j < 2; j++) {
            int ocr = m0 + j * 64;
            const __half* src =
                wsrc + ((size_t)tap * OCROWS + oc0 + ocr) * 256 + icc + cw0 * 8;
            cpa16p(dstB0 + b * bufstride + (ocr * PAD + cw0 * 4) * 4, src, 16);
        }
        asm volatile("cp.async.commit_group;");
    };

    load_chunk(0, 0);

    for (int s = 0; s < NSTAGES; s++) {
        int b = s & 1;
        if (s + 1 < NSTAGES) {
            load_chunk(s + 1, b ^ 1);
            asm volatile("cp.async.wait_group 1;");
        } else {
            asm volatile("cp.async.wait_group 0;");
        }
        __syncthreads();

        const uint32_t* sA = sbuf[b][0];
        const uint32_t* sB = sbuf[b][1];
#pragma unroll
        for (int kb = 0; kb < 2; kb++) {
            int kw = kb * 8;
            uint32_t A[4][4], B[4][2];
#pragma unroll
            for (int mt = 0; mt < 4; mt++) {
                int r = mwarp + mt * 16 + g;
                A[mt][0] = sA[r * PAD + kw + t4];
                A[mt][1] = sA[(r + 8) * PAD + kw + t4];
                A[mt][2] = sA[r * PAD + kw + t4 + 4];
                A[mt][3] = sA[(r + 8) * PAD + kw + t4 + 4];
            }
#pragma unroll
            for (int nt = 0; nt < 4; nt++) {
                int cc = nwarp + nt * 8 + g;
                B[nt][0] = sB[cc * PAD + kw + t4];
                B[nt][1] = sB[cc * PAD + kw + t4 + 4];
            }
#pragma unroll
            for (int mt = 0; mt < 4; mt++)
#pragma unroll
                for (int nt = 0; nt < 4; nt++) {
                    asm volatile(
                        "mma.sync.aligned.m16n8k16.row.col.f32.f16.f16.f32 "
                        "{%0,%1,%2,%3}, {%4,%5,%6,%7}, {%8,%9}, {%0,%1,%2,%3};"
                        : "+f"(acc[mt][nt][0]), "+f"(acc[mt][nt][1]),
                          "+f"(acc[mt][nt][2]), "+f"(acc[mt][nt][3])
                        : "r"(A[mt][0]), "r"(A[mt][1]), "r"(A[mt][2]), "r"(A[mt][3]),
                          "r"(B[nt][0]), "r"(B[nt][1]));
                }
        }
        __syncthreads();
    }

    // epilogue
#pragma unroll
    for (int nt = 0; nt < 4; nt++) {
        int oc = oc0 + nwarp + nt * 8 + 2 * t4;
#pragma unroll
        for (int mt = 0; mt < 4; mt++) {
#pragma unroll
            for (int half_ = 0; half_ < 2; half_++) {
                int r = mwarp + mt * 16 + g + half_ * 8;
                if (p0 + r >= P) continue;
                float v0 = acc[mt][nt][half_ * 2];
                float v1 = acc[mt][nt][half_ * 2 + 1];
                if (mode == 0) {
                    size_t ob = (size_t)(p0 + r) * 256 + oc;
                    out[ob] = v0 + __ldg(&bias[oc]);
                    out[ob + 1] = v1 + __ldg(&bias[oc + 1]);
                } else if (oc < OC) {
                    long long unit =
                        (long long)sn[r] * TP + levelBase + syy[r] * W + sxx[r];
                    v0 += __ldg(&bias[oc]);
                    v1 += __ldg(&bias[oc + 1]);
                    if (mode == 1) {
                        out[unit * 80 + oc] = v0;
                        out[unit * 80 + oc + 1] = v1;
                    } else {
                        if (c_relu[oc]) v0 = fmaxf(v0, 0.f);
                        if (c_relu[oc + 1]) v1 = fmaxf(v1, 0.f);
                        out[c_base[oc] + unit * c_ctot[oc] + c_ch[oc]] = v0;
                        out[c_base[oc + 1] + unit * c_ctot[oc + 1] + c_ch[oc + 1]] = v1;
                    }
                }
            }
        }
    }
}

// ---------------------------------------------------------------------------
// GroupNorm on fp32 NHWC
// ---------------------------------------------------------------------------
__global__ void gn_reduce(const float* __restrict__ y, int HW) {
    int ng = blockIdx.x;
    int n = ng >> 5, gr = ng & 31;
    int tid = threadIdx.x;
    int c8 = tid & 7;
    float s = 0.f, sq = 0.f;
    for (int p = tid >> 3; p < HW; p += 32) {
        float v = y[((size_t)(n * HW + p)) * 256 + gr * 8 + c8];
        s += v;
        sq += v * v;
    }
    __shared__ float ss[256], ssq[256];
    ss[tid] = s; ssq[tid] = sq;
    __syncthreads();
    for (int off = 128; off > 0; off >>= 1) {
        if (tid < off) { ss[tid] += ss[tid + off]; ssq[tid] += ssq[tid + off]; }
        __syncthreads();
    }
    if (tid == 0) {
        float M = 8.f * HW;
        float mu = ss[0] / M;
        float var = ssq[0] / M - mu * mu;
        g_mean[ng] = mu;
        g_inv[ng] = rsqrtf(var + 1e-5f);
    }
}

__global__ void gn_apply(const float* __restrict__ y, __half* __restrict__ act,
                         const float* __restrict__ gamma,
                         const float* __restrict__ beta, int HW, int total) {
    int i = blockIdx.x * blockDim.x + threadIdx.x;
    if (i >= total) return;
    int c = i & 255;
    int p = i >> 8;
    int n = p >= HW ? 1 : 0;
    int ng = n * 32 + (c >> 3);
    float v = (y[i] - g_mean[ng]) * g_inv[ng] * gamma[c] + beta[c];
    act[i] = __float2half_rn(fmaxf(v, 0.f));
}

// ---------------------------------------------------------------------------
// Host orchestration
// ---------------------------------------------------------------------------
extern "C" void kernel_launch(void* const* d_in, const int* in_sizes, int n_in,
                              void* d_out, int out_size) {
    const float* feats[5];
    for (int i = 0; i < 5; i++) feats[i] = (const float*)d_in[i];
    const float* cls_conv_w = (const float*)d_in[5];
    const float* cls_conv_b = (const float*)d_in[6];
    const float* cls_gn_w = (const float*)d_in[7];
    const float* cls_gn_b = (const float*)d_in[8];
    const float* cls_out_w = (const float*)d_in[9];
    const float* cls_out_b = (const float*)d_in[10];
    const float* reg_conv_w = (const float*)d_in[11];
    const float* reg_conv_b = (const float*)d_in[12];
    const float* reg_gn_w = (const float*)d_in[13];
    const float* reg_gn_b = (const float*)d_in[14];
    float* out = (float*)d_out;

    __half *xh, *actA, *actB, *wtc, *wtr, *wtco, *wtro;
    float *ybuf, *regw, *regb;
    cudaGetSymbolAddress((void**)&xh, g_xh);
    cudaGetSymbolAddress((void**)&actA, g_actA);
    cudaGetSymbolAddress((void**)&actB, g_actB);
    cudaGetSymbolAddress((void**)&ybuf, g_y);
    cudaGetSymbolAddress((void**)&regw, g_regw);
    cudaGetSymbolAddress((void**)&regb, g_regb);
    cudaGetSymbolAddress((void**)&wtc, g_wt_cls);
    cudaGetSymbolAddress((void**)&wtr, g_wt_reg);
    cudaGetSymbolAddress((void**)&wtco, g_wtc_out);
    cudaGetSymbolAddress((void**)&wtro, g_wtr_out);

    pack_reg<<<(26 * 2304 + 255) / 256, 256>>>(
        (const float*)d_in[15], (const float*)d_in[16],
        (const float*)d_in[17], (const float*)d_in[18],
        (const float*)d_in[19], (const float*)d_in[20],
        (const float*)d_in[21], (const float*)d_in[22],
        (const float*)d_in[23], (const float*)d_in[24],
        (const float*)d_in[25], (const float*)d_in[26]);

    int wtN = 4 * 9 * 256 * 256;
    pack_wt<<<(wtN + 255) / 256, 256>>>(cls_conv_w, wtc);
    pack_wt<<<(wtN + 255) / 256, 256>>>(reg_conv_w, wtr);
    int hN = 2 * 9 * 128 * 256;
    pack_headw<<<(hN + 255) / 256, 256>>>(cls_out_w, wtco, 80);
    pack_headw<<<(hN + 255) / 256, 256>>>(regw, wtro, 26);

    const int Hs[5] = {100, 50, 25, 13, 7};
    const int Ws[5] = {152, 76, 38, 19, 10};
    const int lvlBase[5] = {0, 15200, 19000, 19950, 20197};

    for (int lvl = 0; lvl < 5; lvl++) {
        int H = Hs[lvl], W = Ws[lvl];
        int HW = H * W;
        int total = 2 * 256 * HW;
        int P = 2 * HW;
        int Mtiles = (P + 127) / 128;
        int gApply = (total + 255) / 256;

        {
            dim3 gT((HW + 31) / 32, 8, 2);
            to_nhwc_half<<<gT, dim3(32, 32)>>>(feats[lvl], xh, HW);
        }

        __half* acts[2] = {actA, actB};

        // --- cls tower + head ---
        const __half* cur = xh;
        for (int s = 0; s < 4; s++) {
            gemm16<<<dim3(Mtiles, 2), 256>>>(cur, wtc + (size_t)s * 589824,
                                             cls_conv_b + s * 256, ybuf, H, W, HW, P,
                                             256, 72, 0, 0, 256);
            gn_reduce<<<64, 256>>>(ybuf, HW);
            gn_apply<<<gApply, 256>>>(ybuf, acts[s & 1], cls_gn_w + s * 256,
                                      cls_gn_b + s * 256, HW, total);
            cur = acts[s & 1];
        }
        gemm16<<<dim3(Mtiles, 1), 256>>>(cur, wtco, cls_out_b, out, H, W, HW, P,
                                         128, 144, 1, lvlBase[lvl], 80);

        // --- reg tower + head ---
        cur = xh;
        for (int s = 0; s < 4; s++) {
            gemm16<<<dim3(Mtiles, 2), 256>>>(cur, wtr + (size_t)s * 589824,
                                             reg_conv_b + s * 256, ybuf, H, W, HW, P,
                                             256, 72, 0, 0, 256);
            gn_reduce<<<64, 256>>>(ybuf, HW);
            gn_apply<<<gApply, 256>>>(ybuf, acts[s & 1], reg_gn_w + s * 256,
                                      reg_gn_b + s * 256, HW, total);
            cur = acts[s & 1];
        }
        gemm16<<<dim3(Mtiles, 1), 256>>>(cur, wtro, regb, out, H, W, HW, P,
                                         128, 144, 2, lvlBase[lvl], 26);
    }
    (void)in_sizes; (void)n_in; (void)out_size;
}

// round 6
// speedup vs baseline: 10.1132x; 2.2381x over previous
#include <cuda_runtime.h>
#include <cuda_fp16.h>
#include <cstdint>

// ---------------------------------------------------------------------------
// FCOS head, fp16 mma.sync (m16n8k16, fp32 accum), level-batched launches.
// Activations NHWC half, levels concatenated. conv3x3 = 9 shifted GEMM taps.
// ---------------------------------------------------------------------------

#define TP 20267
#define TOTE 10376704          // total NHWC elements (all levels, both batch)
#define PAD 20                 // smem row pitch in uint32 words
#define NTILES 319             // total M-tiles over all levels

__device__ __half g_xh[TOTE];
__device__ __half g_actA[TOTE];
__device__ __half g_actB[TOTE];
__device__ __half g_actC[TOTE];
__device__ float  g_y[TOTE];
__device__ float  g_mean[5 * 64];
__device__ float  g_inv[5 * 64];
__device__ float  g_regw[26 * 256 * 9];
__device__ float  g_regb[26];
__device__ __half g_wt_cls[4 * 9 * 256 * 256];   // [s][tap][oc][ic]
__device__ __half g_wt_reg[4 * 9 * 256 * 256];
__device__ __half g_wtc_out[2 * 9 * 128 * 256];  // [part][tap][ocpad][ic]
__device__ __half g_wtr_out[2 * 9 * 128 * 256];

__constant__ int c_Hs[5] = {100, 50, 25, 13, 7};
__constant__ int c_Ws[5] = {152, 76, 38, 19, 10};
__constant__ int c_HWs[5] = {15200, 3800, 950, 247, 70};
__constant__ int c_Ps[5] = {30400, 7600, 1900, 494, 140};
__constant__ int c_tb[5] = {0, 238, 298, 313, 317};
__constant__ int c_ao[5] = {0, 7782400, 9728000, 10214400, 10340864};
__constant__ int c_lb[5] = {0, 15200, 19000, 19950, 20197};

__constant__ long long c_base[26] = {
    3242720LL, 3242720LL, 3242720LL, 3242720LL,
    3404856LL,
    3445390LL, 3445390LL, 3445390LL,
    3566992LL,
    3607526LL, 3607526LL, 3607526LL, 3607526LL, 3607526LL, 3607526LL,
    3607526LL, 3607526LL, 3607526LL, 3607526LL, 3607526LL, 3607526LL,
    3607526LL, 3607526LL, 3607526LL, 3607526LL,
    4256070LL};
__constant__ int c_ctot[26] = {4, 4, 4, 4, 1, 3, 3, 3, 1,
                               16, 16, 16, 16, 16, 16, 16, 16,
                               16, 16, 16, 16, 16, 16, 16, 16, 1};
__constant__ int c_ch[26] = {0, 1, 2, 3, 0, 0, 1, 2, 0,
                             0, 1, 2, 3, 4, 5, 6, 7,
                             8, 9, 10, 11, 12, 13, 14, 15, 0};
__constant__ int c_relu[26] = {1, 1, 1, 1, 0, 0, 0, 0, 0,
                               0, 0, 0, 0, 0, 0, 0, 0,
                               0, 0, 0, 0, 0, 0, 0, 0, 0};

__device__ __forceinline__ void cpa16p(uint32_t d, const void* s, int sz) {
    asm volatile("cp.async.cg.shared.global [%0], [%1], 16, %2;" ::"r"(d), "l"(s), "r"(sz));
}
#define LDSM4(r0, r1, r2, r3, a)                                           \
    asm volatile("ldmatrix.sync.aligned.m8n8.x4.shared.b16 {%0,%1,%2,%3}, [%4];" \
                 : "=r"(r0), "=r"(r1), "=r"(r2), "=r"(r3) : "r"(a))

// ---------------------------------------------------------------------------
// NCHW fp32 -> NHWC half (per level)
// ---------------------------------------------------------------------------
__global__ void to_nhwc_half(const float* __restrict__ src, __half* __restrict__ dst,
                             int HW) {
    __shared__ float t[32][33];
    int n = blockIdx.z;
    int p0 = blockIdx.x * 32, c0 = blockIdx.y * 32;
    int tx = threadIdx.x, ty = threadIdx.y;
    int p = p0 + tx;
    if (p < HW) t[ty][tx] = src[((size_t)(n * 256 + c0 + ty)) * HW + p];
    __syncthreads();
    int p2 = p0 + ty, c2 = c0 + tx;
    if (p2 < HW) dst[((size_t)(n * HW + p2)) * 256 + c2] = __float2half_rn(t[tx][ty]);
}

// ---------------------------------------------------------------------------
// Weight packs
// ---------------------------------------------------------------------------
__global__ void pack_wt(const float* __restrict__ w, __half* __restrict__ wt) {
    int idx = blockIdx.x * blockDim.x + threadIdx.x;
    if (idx >= 4 * 9 * 256 * 256) return;
    int ic = idx & 255;
    int oc = (idx >> 8) & 255;
    int tap = (idx >> 16) % 9;
    int s = idx / 589824;
    wt[idx] = __float2half_rn(w[(((size_t)(s * 256 + oc) * 256 + ic) * 9) + tap]);
}

__global__ void pack_headw(const float* __restrict__ src, __half* __restrict__ dst,
                           int OC) {
    int idx = blockIdx.x * blockDim.x + threadIdx.x;
    if (idx >= 2 * 9 * 128 * 256) return;
    int ic = idx & 255;
    int oc = (idx >> 8) & 127;
    int tap = (idx >> 15) % 9;
    int part = idx / (9 * 128 * 256);
    float v = 0.f;
    if (oc < OC) v = src[((size_t)oc * 256 + ic) * 9 + tap];
    __half hi = __float2half_rn(v);
    dst[idx] = (part == 0) ? hi : __float2half_rn(v - __half2float(hi));
}

__global__ void pack_reg(const float* __restrict__ bbox_w, const float* __restrict__ bbox_b,
                         const float* __restrict__ ctr_w,  const float* __restrict__ ctr_b,
                         const float* __restrict__ dim_w,  const float* __restrict__ dim_b,
                         const float* __restrict__ ori_w,  const float* __restrict__ ori_b,
                         const float* __restrict__ kp_w,   const float* __restrict__ kp_b,
                         const float* __restrict__ depth_w,const float* __restrict__ depth_b) {
    int idx = blockIdx.x * blockDim.x + threadIdx.x;
    int total = 26 * 2304;
    if (idx < total) {
        int oc = idx / 2304;
        int r = idx % 2304;
        const float* src;
        if (oc < 4)       src = bbox_w + oc * 2304;
        else if (oc == 4) src = ctr_w;
        else if (oc < 8)  src = dim_w + (oc - 5) * 2304;
        else if (oc == 8) src = ori_w;
        else if (oc < 25) src = kp_w + (oc - 9) * 2304;
        else              src = depth_w;
        g_regw[idx] = src[r];
    }
    if (idx < 26) {
        float b;
        if (idx < 4)       b = bbox_b[idx];
        else if (idx == 4) b = ctr_b[0];
        else if (idx < 8)  b = dim_b[idx - 5];
        else if (idx == 8) b = ori_b[0];
        else if (idx < 25) b = kp_b[idx - 9];
        else               b = depth_b[0];
        g_regb[idx] = b;
    }
}

// ---------------------------------------------------------------------------
// Level-batched fp16 implicit-GEMM conv. M=128 pos x N=128 oc.
// kind 0: tower. grid (NTILES, 2): blockIdx.y = oc half; out = fp32 NHWC y.
// kind 1: heads. grid (NTILES, 2): blockIdx.y = 0 cls / 1 reg; out = d_out.
// ---------------------------------------------------------------------------
__global__ __launch_bounds__(256, 2) void gemm16(
    const __half* __restrict__ x0, const __half* __restrict__ x1,
    const __half* __restrict__ wt0, const __half* __restrict__ wt1,
    const float* __restrict__ b0p, const float* __restrict__ b1p,
    float* __restrict__ out, int NST, int kind) {
    __shared__ uint32_t sbuf[2][2][128 * PAD];
    __shared__ int syy[128], sxx[128], sn[128];

    int tid = threadIdx.x;
    int bx = blockIdx.x, by = blockIdx.y;
    int lvl = (bx >= c_tb[1]) + (bx >= c_tb[2]) + (bx >= c_tb[3]) + (bx >= c_tb[4]);
    int H = c_Hs[lvl], W = c_Ws[lvl], HW = c_HWs[lvl], P = c_Ps[lvl];
    int p0 = (bx - c_tb[lvl]) * 128;

    const __half* x;
    const __half* wt;
    const float* bias;
    int oc0, OC;
    if (kind == 0) {
        x = x0 + c_ao[lvl];
        wt = wt0;
        bias = b0p;
        oc0 = by * 128;
        OC = 256;
    } else {
        x = (by ? x1 : x0) + c_ao[lvl];
        wt = by ? wt1 : wt0;
        bias = by ? b1p : b0p;
        oc0 = 0;
        OC = by ? 26 : 80;
    }

    if (tid < 128) {
        int p = p0 + tid;
        if (p < P) {
            int n = p >= HW ? 1 : 0;
            int rr = p - n * HW;
            int yy = rr / W;
            syy[tid] = yy;
            sxx[tid] = rr - yy * W;
            sn[tid] = n;
        } else {
            syy[tid] = -100000;
            sxx[tid] = -100000;
            sn[tid] = 0;
        }
    }
    __syncthreads();

    int warp = tid >> 5, lane = tid & 31, g = lane >> 2, t4 = lane & 3;
    int mwarp = (warp >> 2) * 64, nwarp = (warp & 3) * 32;

    float acc[4][4][4];
#pragma unroll
    for (int i = 0; i < 4; i++)
#pragma unroll
        for (int j = 0; j < 4; j++)
#pragma unroll
            for (int q = 0; q < 4; q++) acc[i][j][q] = 0.f;

    int m0 = tid >> 2, cw0 = tid & 3;
    uint32_t dstA0 = (uint32_t)__cvta_generic_to_shared(&sbuf[0][0][0]);
    uint32_t dstB0 = (uint32_t)__cvta_generic_to_shared(&sbuf[0][1][0]);
    const uint32_t bufstride = 2 * 128 * PAD * 4;

    // ldmatrix lane addressing
    int laneA_row = lane & 15;
    int colA = (lane >> 4) * 4;
    int laneB_row = ((lane >> 4) << 3) + (lane & 7);
    int colB = ((lane >> 3) & 1) * 4;
    uint32_t aAf[2], aBf[2];
#pragma unroll
    for (int b = 0; b < 2; b++) {
        aAf[b] = dstA0 + b * bufstride + ((mwarp + laneA_row) * PAD + colA) * 4;
        aBf[b] = dstB0 + b * bufstride + ((nwarp + laneB_row) * PAD + colB) * 4;
    }

    auto load_chunk = [&](int c, int b) {
        int cc = c, part = 0;
        if (kind) { cc = c % 72; part = c / 72; }
        int tap = cc >> 3;
        int icc = (cc & 7) << 5;
        int ty = tap / 3;
        int dy = ty - 1, dx = tap - ty * 3 - 1;
#pragma unroll
        for (int j = 0; j < 2; j++) {
            int m = m0 + j * 64;
            int gy = syy[m] + dy, gx = sxx[m] + dx;
            bool v = ((unsigned)gy < (unsigned)H) && ((unsigned)gx < (unsigned)W);
            const __half* src =
                x + ((size_t)(sn[m] * HW + gy * W + gx) * 256 + icc + cw0 * 8);
            cpa16p(dstA0 + b * bufstride + (m * PAD + cw0 * 4) * 4,
                   v ? src : (const __half*)x, v ? 16 : 0);
        }
        const __half* wbase =
            kind ? wt + ((size_t)((part * 9 + tap) * 128)) * 256
                 : wt + ((size_t)(tap * 256 + oc0)) * 256;
#pragma unroll
        for (int j = 0; j < 2; j++) {
            int ocr = m0 + j * 64;
            cpa16p(dstB0 + b * bufstride + (ocr * PAD + cw0 * 4) * 4,
                   wbase + (size_t)ocr * 256 + icc + cw0 * 8, 16);
        }
        asm volatile("cp.async.commit_group;");
    };

    load_chunk(0, 0);

    for (int s = 0; s < NST; s++) {
        int b = s & 1;
        if (s + 1 < NST) {
            load_chunk(s + 1, b ^ 1);
            asm volatile("cp.async.wait_group 1;");
        } else {
            asm volatile("cp.async.wait_group 0;");
        }
        __syncthreads();

#pragma unroll
        for (int kb = 0; kb < 2; kb++) {
            uint32_t kwb = kb * 8 * 4;
            uint32_t A[4][4], Bv[2][4];
#pragma unroll
            for (int mt = 0; mt < 4; mt++)
                LDSM4(A[mt][0], A[mt][1], A[mt][2], A[mt][3],
                      aAf[b] + mt * (16 * PAD * 4) + kwb);
#pragma unroll
            for (int ntp = 0; ntp < 2; ntp++)
                LDSM4(Bv[ntp][0], Bv[ntp][1], Bv[ntp][2], Bv[ntp][3],
                      aBf[b] + ntp * (16 * PAD * 4) + kwb);
#pragma unroll
            for (int mt = 0; mt < 4; mt++)
#pragma unroll
                for (int nt = 0; nt < 4; nt++) {
                    int ntp = nt >> 1, j = nt & 1;
                    asm volatile(
                        "mma.sync.aligned.m16n8k16.row.col.f32.f16.f16.f32 "
                        "{%0,%1,%2,%3}, {%4,%5,%6,%7}, {%8,%9}, {%0,%1,%2,%3};"
                        : "+f"(acc[mt][nt][0]), "+f"(acc[mt][nt][1]),
                          "+f"(acc[mt][nt][2]), "+f"(acc[mt][nt][3])
                        : "r"(A[mt][0]), "r"(A[mt][1]), "r"(A[mt][2]), "r"(A[mt][3]),
                          "r"(Bv[ntp][j * 2]), "r"(Bv[ntp][j * 2 + 1]));
                }
        }
        __syncthreads();
    }

    // epilogue
#pragma unroll
    for (int nt = 0; nt < 4; nt++) {
        int oc = oc0 + nwarp + nt * 8 + 2 * t4;
#pragma unroll
        for (int mt = 0; mt < 4; mt++) {
#pragma unroll
            for (int hf = 0; hf < 2; hf++) {
                int r = mwarp + mt * 16 + g + hf * 8;
                if (p0 + r >= P) continue;
                float v0 = acc[mt][nt][hf * 2];
                float v1 = acc[mt][nt][hf * 2 + 1];
                if (kind == 0) {
                    size_t ob = (size_t)c_ao[lvl] + (size_t)(p0 + r) * 256 + oc;
                    float2 st = {v0 + __ldg(&bias[oc]), v1 + __ldg(&bias[oc + 1])};
                    *(float2*)&out[ob] = st;
                } else if (oc < OC) {
                    long long unit =
                        (long long)sn[r] * TP + c_lb[lvl] + syy[r] * W + sxx[r];
                    v0 += __ldg(&bias[oc]);
                    v1 += __ldg(&bias[oc + 1]);
                    if (by == 0) {
                        out[unit * 80 + oc] = v0;
                        out[unit * 80 + oc + 1] = v1;
                    } else {
                        if (c_relu[oc]) v0 = fmaxf(v0, 0.f);
                        if (c_relu[oc + 1]) v1 = fmaxf(v1, 0.f);
                        out[c_base[oc] + unit * c_ctot[oc] + c_ch[oc]] = v0;
                        out[c_base[oc + 1] + unit * c_ctot[oc + 1] + c_ch[oc + 1]] = v1;
                    }
                }
            }
        }
    }
}

// ---------------------------------------------------------------------------
// GroupNorm (level-batched): grid 320 = 5 levels x 64 (n,group)
// ---------------------------------------------------------------------------
__global__ void gn_reduce(const float* __restrict__ y) {
    int l = blockIdx.x >> 6;
    int ng = blockIdx.x & 63;
    int n = ng >> 5, gr = ng & 31;
    int HW = c_HWs[l];
    const float* base = y + c_ao[l] + (size_t)n * HW * 256 + gr * 8 + (threadIdx.x & 1) * 4;
    int tid = threadIdx.x;
    float s = 0.f, sq = 0.f;
    for (int p = tid >> 1; p < HW; p += 128) {
        float4 v = *(const float4*)&base[(size_t)p * 256];
        s += v.x + v.y + v.z + v.w;
        sq += v.x * v.x + v.y * v.y + v.z * v.z + v.w * v.w;
    }
    __shared__ float ss[256], ssq[256];
    ss[tid] = s; ssq[tid] = sq;
    __syncthreads();
    for (int off = 128; off > 0; off >>= 1) {
        if (tid < off) { ss[tid] += ss[tid + off]; ssq[tid] += ssq[tid + off]; }
        __syncthreads();
    }
    if (tid == 0) {
        float M = 8.f * HW;
        float mu = ss[0] / M;
        float var = ssq[0] / M - mu * mu;
        g_mean[blockIdx.x] = mu;
        g_inv[blockIdx.x] = rsqrtf(var + 1e-5f);
    }
}

__global__ void gn_apply(const float* __restrict__ y, __half* __restrict__ act,
                         const float* __restrict__ gamma,
                         const float* __restrict__ beta) {
    int idx = blockIdx.x * blockDim.x + threadIdx.x;
    if (idx >= TOTE / 4) return;
    int e = idx * 4;
    int l = (e >= c_ao[1]) + (e >= c_ao[2]) + (e >= c_ao[3]) + (e >= c_ao[4]);
    int c = e & 255;
    int pl = (e - c_ao[l]) >> 8;
    int n = pl >= c_HWs[l] ? 1 : 0;
    int ng = l * 64 + n * 32 + (c >> 3);
    float mu = g_mean[ng], iv = g_inv[ng];
    float4 v = *(const float4*)&y[e];
    float4 gm = *(const float4*)&gamma[c];
    float4 bt = *(const float4*)&beta[c];
    __half2 h0 = __floats2half2_rn(fmaxf((v.x - mu) * iv * gm.x + bt.x, 0.f),
                                   fmaxf((v.y - mu) * iv * gm.y + bt.y, 0.f));
    __half2 h1 = __floats2half2_rn(fmaxf((v.z - mu) * iv * gm.z + bt.z, 0.f),
                                   fmaxf((v.w - mu) * iv * gm.w + bt.w, 0.f));
    uint2 st = {*(uint32_t*)&h0, *(uint32_t*)&h1};
    *(uint2*)&act[e] = st;
}

// ---------------------------------------------------------------------------
// Host orchestration
// ---------------------------------------------------------------------------
extern "C" void kernel_launch(void* const* d_in, const int* in_sizes, int n_in,
                              void* d_out, int out_size) {
    const float* feats[5];
    for (int i = 0; i < 5; i++) feats[i] = (const float*)d_in[i];
    const float* cls_conv_w = (const float*)d_in[5];
    const float* cls_conv_b = (const float*)d_in[6];
    const float* cls_gn_w = (const float*)d_in[7];
    const float* cls_gn_b = (const float*)d_in[8];
    const float* cls_out_w = (const float*)d_in[9];
    const float* cls_out_b = (const float*)d_in[10];
    const float* reg_conv_w = (const float*)d_in[11];
    const float* reg_conv_b = (const float*)d_in[12];
    const float* reg_gn_w = (const float*)d_in[13];
    const float* reg_gn_b = (const float*)d_in[14];
    float* out = (float*)d_out;

    __half *xh, *actA, *actB, *actC, *wtc, *wtr, *wtco, *wtro;
    float *ybuf, *regw, *regb;
    cudaGetSymbolAddress((void**)&xh, g_xh);
    cudaGetSymbolAddress((void**)&actA, g_actA);
    cudaGetSymbolAddress((void**)&actB, g_actB);
    cudaGetSymbolAddress((void**)&actC, g_actC);
    cudaGetSymbolAddress((void**)&ybuf, g_y);
    cudaGetSymbolAddress((void**)&regw, g_regw);
    cudaGetSymbolAddress((void**)&regb, g_regb);
    cudaGetSymbolAddress((void**)&wtc, g_wt_cls);
    cudaGetSymbolAddress((void**)&wtr, g_wt_reg);
    cudaGetSymbolAddress((void**)&wtco, g_wtc_out);
    cudaGetSymbolAddress((void**)&wtro, g_wtr_out);

    pack_reg<<<(26 * 2304 + 255) / 256, 256>>>(
        (const float*)d_in[15], (const float*)d_in[16],
        (const float*)d_in[17], (const float*)d_in[18],
        (const float*)d_in[19], (const float*)d_in[20],
        (const float*)d_in[21], (const float*)d_in[22],
        (const float*)d_in[23], (const float*)d_in[24],
        (const float*)d_in[25], (const float*)d_in[26]);

    int wtN = 4 * 9 * 256 * 256;
    pack_wt<<<(wtN + 255) / 256, 256>>>(cls_conv_w, wtc);
    pack_wt<<<(wtN + 255) / 256, 256>>>(reg_conv_w, wtr);
    int hN = 2 * 9 * 128 * 256;
    pack_headw<<<(hN + 255) / 256, 256>>>(cls_out_w, wtco, 80);
    pack_headw<<<(hN + 255) / 256, 256>>>(regw, wtro, 26);

    const int Hws[5] = {15200, 3800, 950, 247, 70};
    const int aoH[5] = {0, 7782400, 9728000, 10214400, 10340864};
    for (int l = 0; l < 5; l++) {
        dim3 gT((Hws[l] + 31) / 32, 8, 2);
        to_nhwc_half<<<gT, dim3(32, 32)>>>(feats[l], xh + aoH[l], Hws[l]);
    }

    int gApply = (TOTE / 4 + 255) / 256;

    // cls tower: xh->A->B->A->B
    const __half* cur = xh;
    __half* dsts[4] = {actA, actB, actA, actB};
    for (int s = 0; s < 4; s++) {
        gemm16<<<dim3(NTILES, 2), 256>>>(cur, nullptr, wtc + (size_t)s * 589824,
                                         nullptr, cls_conv_b + s * 256, nullptr,
                                         ybuf, 72, 0);
        gn_reduce<<<320, 256>>>(ybuf);
        gn_apply<<<gApply, 256>>>(ybuf, dsts[s], cls_gn_w + s * 256,
                                  cls_gn_b + s * 256);
        cur = dsts[s];
    }
    // reg tower: xh->C->A? no: C,A would clobber cls. use C and A after cls done
    // cls final is actB; reg: xh->C, C->A, A->C, C->A (final A)
    cur = xh;
    __half* dstr[4] = {actC, actA, actC, actA};
    for (int s = 0; s < 4; s++) {
        gemm16<<<dim3(NTILES, 2), 256>>>(cur, nullptr, wtr + (size_t)s * 589824,
                                         nullptr, reg_conv_b + s * 256, nullptr,
                                         ybuf, 72, 0);
        gn_reduce<<<320, 256>>>(ybuf);
        gn_apply<<<gApply, 256>>>(ybuf, dstr[s], reg_gn_w + s * 256,
                                  reg_gn_b + s * 256);
        cur = dstr[s];
    }
    // combined heads: by 0 = cls (reads actB), by 1 = reg (reads actA)
    gemm16<<<dim3(NTILES, 2), 256>>>(actB, actA, wtco, wtro, cls_out_b, regb,
                                     out, 144, 1);
    (void)in_sizes; (void)n_in; (void)out_size;
}

// round 7
// speedup vs baseline: 12.2823x; 1.2145x over previous
#include <cuda_runtime.h>
#include <cuda_fp16.h>
#include <cstdint>

// ---------------------------------------------------------------------------
// FCOS head, fp16 mma.sync (m16n8k16, fp32 accum). Level-batched, path-batched
// (cls+reg in one launch), 4-deep cp.async pipeline.
// ---------------------------------------------------------------------------

#define TP 20267
#define TOTE 10376704          // total NHWC elements (all levels, both batch)
#define PAD 20                 // smem row pitch in uint32 words
#define NTILES 319             // total M-tiles over all levels
#define STAGE_BYTES 20480      // per pipeline slot: A(10240) + B(10240)
#define DYN_SMEM (4 * STAGE_BYTES)

__device__ __half g_xh[TOTE];
__device__ __half g_actA[TOTE];   // cls ping
__device__ __half g_actB[TOTE];   // cls pong
__device__ __half g_actC[TOTE];   // reg ping
__device__ __half g_actD[TOTE];   // reg pong
__device__ float  g_y[TOTE];      // cls conv out
__device__ float  g_y2[TOTE];     // reg conv out
__device__ float  g_mean[640];
__device__ float  g_inv[640];
__device__ float  g_regw[26 * 256 * 9];
__device__ float  g_regb[26];
__device__ __half g_wt_cls[4 * 9 * 256 * 256];   // [s][tap][oc][ic]
__device__ __half g_wt_reg[4 * 9 * 256 * 256];
__device__ __half g_wtc_out[2 * 9 * 128 * 256];  // [part][tap][ocpad][ic]
__device__ __half g_wtr_out[2 * 9 * 128 * 256];

__constant__ int c_Hs[5] = {100, 50, 25, 13, 7};
__constant__ int c_Ws[5] = {152, 76, 38, 19, 10};
__constant__ int c_HWs[5] = {15200, 3800, 950, 247, 70};
__constant__ int c_Ps[5] = {30400, 7600, 1900, 494, 140};
__constant__ int c_tb[5] = {0, 238, 298, 313, 317};
__constant__ int c_ao[5] = {0, 7782400, 9728000, 10214400, 10340864};
__constant__ int c_lb[5] = {0, 15200, 19000, 19950, 20197};

__constant__ long long c_base[26] = {
    3242720LL, 3242720LL, 3242720LL, 3242720LL,
    3404856LL,
    3445390LL, 3445390LL, 3445390LL,
    3566992LL,
    3607526LL, 3607526LL, 3607526LL, 3607526LL, 3607526LL, 3607526LL,
    3607526LL, 3607526LL, 3607526LL, 3607526LL, 3607526LL, 3607526LL,
    3607526LL, 3607526LL, 3607526LL, 3607526LL,
    4256070LL};
__constant__ int c_ctot[26] = {4, 4, 4, 4, 1, 3, 3, 3, 1,
                               16, 16, 16, 16, 16, 16, 16, 16,
                               16, 16, 16, 16, 16, 16, 16, 16, 1};
__constant__ int c_ch[26] = {0, 1, 2, 3, 0, 0, 1, 2, 0,
                             0, 1, 2, 3, 4, 5, 6, 7,
                             8, 9, 10, 11, 12, 13, 14, 15, 0};
__constant__ int c_relu[26] = {1, 1, 1, 1, 0, 0, 0, 0, 0,
                               0, 0, 0, 0, 0, 0, 0, 0,
                               0, 0, 0, 0, 0, 0, 0, 0, 0};

__device__ __forceinline__ void cpa16p(uint32_t d, const void* s, int sz) {
    asm volatile("cp.async.cg.shared.global [%0], [%1], 16, %2;" ::"r"(d), "l"(s), "r"(sz));
}
#define LDSM4(r0, r1, r2, r3, a)                                           \
    asm volatile("ldmatrix.sync.aligned.m8n8.x4.shared.b16 {%0,%1,%2,%3}, [%4];" \
                 : "=r"(r0), "=r"(r1), "=r"(r2), "=r"(r3) : "r"(a))

// ---------------------------------------------------------------------------
// NCHW fp32 -> NHWC half, all levels in one launch. grid (475, 8, 10)
// ---------------------------------------------------------------------------
__global__ void to_nhwc_half(const float* __restrict__ f0, const float* __restrict__ f1,
                             const float* __restrict__ f2, const float* __restrict__ f3,
                             const float* __restrict__ f4, __half* __restrict__ xh) {
    __shared__ float t[32][33];
    int z = blockIdx.z;
    int lvl = z >> 1, n = z & 1;
    int HW = c_HWs[lvl];
    int p0 = blockIdx.x * 32;
    if (p0 >= HW) return;
    const float* src = lvl == 0 ? f0 : lvl == 1 ? f1 : lvl == 2 ? f2 : lvl == 3 ? f3 : f4;
    __half* dst = xh + c_ao[lvl];
    int c0 = blockIdx.y * 32;
    int tx = threadIdx.x, ty = threadIdx.y;
    int p = p0 + tx;
    if (p < HW) t[ty][tx] = src[((size_t)(n * 256 + c0 + ty)) * HW + p];
    __syncthreads();
    int p2 = p0 + ty, c2 = c0 + tx;
    if (p2 < HW) dst[((size_t)(n * HW + p2)) * 256 + c2] = __float2half_rn(t[tx][ty]);
}

// ---------------------------------------------------------------------------
// Weight packs
// ---------------------------------------------------------------------------
__global__ void pack_wt(const float* __restrict__ w, __half* __restrict__ wt) {
    int idx = blockIdx.x * blockDim.x + threadIdx.x;
    if (idx >= 4 * 9 * 256 * 256) return;
    int ic = idx & 255;
    int oc = (idx >> 8) & 255;
    int tap = (idx >> 16) % 9;
    int s = idx / 589824;
    wt[idx] = __float2half_rn(w[(((size_t)(s * 256 + oc) * 256 + ic) * 9) + tap]);
}

__global__ void pack_headw(const float* __restrict__ src, __half* __restrict__ dst,
                           int OC) {
    int idx = blockIdx.x * blockDim.x + threadIdx.x;
    if (idx >= 2 * 9 * 128 * 256) return;
    int ic = idx & 255;
    int oc = (idx >> 8) & 127;
    int tap = (idx >> 15) % 9;
    int part = idx / (9 * 128 * 256);
    float v = 0.f;
    if (oc < OC) v = src[((size_t)oc * 256 + ic) * 9 + tap];
    __half hi = __float2half_rn(v);
    dst[idx] = (part == 0) ? hi : __float2half_rn(v - __half2float(hi));
}

__global__ void pack_reg(const float* __restrict__ bbox_w, const float* __restrict__ bbox_b,
                         const float* __restrict__ ctr_w,  const float* __restrict__ ctr_b,
                         const float* __restrict__ dim_w,  const float* __restrict__ dim_b,
                         const float* __restrict__ ori_w,  const float* __restrict__ ori_b,
                         const float* __restrict__ kp_w,   const float* __restrict__ kp_b,
                         const float* __restrict__ depth_w,const float* __restrict__ depth_b) {
    int idx = blockIdx.x * blockDim.x + threadIdx.x;
    int total = 26 * 2304;
    if (idx < total) {
        int oc = idx / 2304;
        int r = idx % 2304;
        const float* src;
        if (oc < 4)       src = bbox_w + oc * 2304;
        else if (oc == 4) src = ctr_w;
        else if (oc < 8)  src = dim_w + (oc - 5) * 2304;
        else if (oc == 8) src = ori_w;
        else if (oc < 25) src = kp_w + (oc - 9) * 2304;
        else              src = depth_w;
        g_regw[idx] = src[r];
    }
    if (idx < 26) {
        float b;
        if (idx < 4)       b = bbox_b[idx];
        else if (idx == 4) b = ctr_b[0];
        else if (idx < 8)  b = dim_b[idx - 5];
        else if (idx == 8) b = ori_b[0];
        else if (idx < 25) b = kp_b[idx - 9];
        else               b = depth_b[0];
        g_regb[idx] = b;
    }
}

// ---------------------------------------------------------------------------
// Path+level-batched fp16 implicit-GEMM conv. M=128 pos x N=128 oc.
// kind 0: towers, grid (NTILES,4): by>>1 = path (cls/reg), by&1 = oc half.
// kind 1: heads,  grid (NTILES,2): by = path. Writes d_out directly.
// Dynamic smem: 4-deep ring of (A 10KB + B 10KB) slots.
// ---------------------------------------------------------------------------
__global__ __launch_bounds__(256, 2) void gemm16(
    const __half* __restrict__ x0, const __half* __restrict__ x1,
    const __half* __restrict__ wt0, const __half* __restrict__ wt1,
    const float* __restrict__ b0p, const float* __restrict__ b1p,
    float* __restrict__ out0, float* __restrict__ out1, int NST, int kind) {
    extern __shared__ __align__(16) uint32_t dynsm[];
    __shared__ int syy[128], sxx[128], sn[128];

    int tid = threadIdx.x;
    int bx = blockIdx.x, by = blockIdx.y;
    int lvl = (bx >= c_tb[1]) + (bx >= c_tb[2]) + (bx >= c_tb[3]) + (bx >= c_tb[4]);
    int H = c_Hs[lvl], W = c_Ws[lvl], HW = c_HWs[lvl], P = c_Ps[lvl];
    int p0 = (bx - c_tb[lvl]) * 128;

    int path, oc0, OC;
    if (kind == 0) {
        path = by >> 1;
        oc0 = (by & 1) * 128;
        OC = 256;
    } else {
        path = by;
        oc0 = 0;
        OC = by ? 26 : 80;
    }
    const __half* x = (path ? x1 : x0) + c_ao[lvl];
    const __half* wt = path ? wt1 : wt0;
    const float* bias = path ? b1p : b0p;
    float* outp = path ? out1 : out0;

    if (tid < 128) {
        int p = p0 + tid;
        if (p < P) {
            int n = p >= HW ? 1 : 0;
            int rr = p - n * HW;
            int yy = rr / W;
            syy[tid] = yy;
            sxx[tid] = rr - yy * W;
            sn[tid] = n;
        } else {
            syy[tid] = -100000;
            sxx[tid] = -100000;
            sn[tid] = 0;
        }
    }
    __syncthreads();

    int warp = tid >> 5, lane = tid & 31, g = lane >> 2, t4 = lane & 3;
    int mwarp = (warp >> 2) * 64, nwarp = (warp & 3) * 32;

    float acc[4][4][4];
#pragma unroll
    for (int i = 0; i < 4; i++)
#pragma unroll
        for (int j = 0; j < 4; j++)
#pragma unroll
            for (int q = 0; q < 4; q++) acc[i][j][q] = 0.f;

    int m0 = tid >> 2, cw0 = tid & 3;
    uint32_t smbase = (uint32_t)__cvta_generic_to_shared(dynsm);

    // ldmatrix lane addressing (within a slot)
    int laneA_row = lane & 15;
    int colA = (lane >> 4) * 4;
    int laneB_row = ((lane >> 4) << 3) + (lane & 7);
    int colB = ((lane >> 3) & 1) * 4;
    uint32_t aAoff = ((mwarp + laneA_row) * PAD + colA) * 4;
    uint32_t aBoff = 10240 + ((nwarp + laneB_row) * PAD + colB) * 4;

    auto load_chunk = [&](int c, int slot) {
        int cc = c, part = 0;
        if (kind) { cc = c % 72; part = c / 72; }
        int tap = cc >> 3;
        int icc = (cc & 7) << 5;
        int ty = tap / 3;
        int dy = ty - 1, dx = tap - ty * 3 - 1;
        uint32_t base = smbase + slot * STAGE_BYTES;
#pragma unroll
        for (int j = 0; j < 2; j++) {
            int m = m0 + j * 64;
            int gy = syy[m] + dy, gx = sxx[m] + dx;
            bool v = ((unsigned)gy < (unsigned)H) && ((unsigned)gx < (unsigned)W);
            const __half* src =
                x + ((size_t)(sn[m] * HW + gy * W + gx) * 256 + icc + cw0 * 8);
            cpa16p(base + (m * PAD + cw0 * 4) * 4, v ? src : (const __half*)x,
                   v ? 16 : 0);
        }
        const __half* wbase =
            kind ? wt + ((size_t)((part * 9 + tap) * 128)) * 256
                 : wt + ((size_t)(tap * 256 + oc0)) * 256;
#pragma unroll
        for (int j = 0; j < 2; j++) {
            int ocr = m0 + j * 64;
            cpa16p(base + 10240 + (ocr * PAD + cw0 * 4) * 4,
                   wbase + (size_t)ocr * 256 + icc + cw0 * 8, 16);
        }
        asm volatile("cp.async.commit_group;");
    };

    load_chunk(0, 0);
    load_chunk(1, 1);
    load_chunk(2, 2);

    for (int s = 0; s < NST; s++) {
        int slot = s & 3;
        if (s + 2 < NST) {
            asm volatile("cp.async.wait_group 2;");
        } else if (s + 1 < NST) {
            asm volatile("cp.async.wait_group 1;");
        } else {
            asm volatile("cp.async.wait_group 0;");
        }
        __syncthreads();
        if (s + 3 < NST) load_chunk(s + 3, (s + 3) & 3);

        uint32_t sb = smbase + slot * STAGE_BYTES;
        uint32_t aA = sb + aAoff;
        uint32_t aB = sb + aBoff;
#pragma unroll
        for (int kb = 0; kb < 2; kb++) {
            uint32_t kwb = kb * 8 * 4;
            uint32_t A[4][4], Bv[2][4];
#pragma unroll
            for (int mt = 0; mt < 4; mt++)
                LDSM4(A[mt][0], A[mt][1], A[mt][2], A[mt][3],
                      aA + mt * (16 * PAD * 4) + kwb);
#pragma unroll
            for (int ntp = 0; ntp < 2; ntp++)
                LDSM4(Bv[ntp][0], Bv[ntp][1], Bv[ntp][2], Bv[ntp][3],
                      aB + ntp * (16 * PAD * 4) + kwb);
#pragma unroll
            for (int mt = 0; mt < 4; mt++)
#pragma unroll
                for (int nt = 0; nt < 4; nt++) {
                    int ntp = nt >> 1, j = nt & 1;
                    asm volatile(
                        "mma.sync.aligned.m16n8k16.row.col.f32.f16.f16.f32 "
                        "{%0,%1,%2,%3}, {%4,%5,%6,%7}, {%8,%9}, {%0,%1,%2,%3};"
                        : "+f"(acc[mt][nt][0]), "+f"(acc[mt][nt][1]),
                          "+f"(acc[mt][nt][2]), "+f"(acc[mt][nt][3])
                        : "r"(A[mt][0]), "r"(A[mt][1]), "r"(A[mt][2]), "r"(A[mt][3]),
                          "r"(Bv[ntp][j * 2]), "r"(Bv[ntp][j * 2 + 1]));
                }
        }
    }

    // epilogue
#pragma unroll
    for (int nt = 0; nt < 4; nt++) {
        int oc = oc0 + nwarp + nt * 8 + 2 * t4;
#pragma unroll
        for (int mt = 0; mt < 4; mt++) {
#pragma unroll
            for (int hf = 0; hf < 2; hf++) {
                int r = mwarp + mt * 16 + g + hf * 8;
                if (p0 + r >= P) continue;
                float v0 = acc[mt][nt][hf * 2];
                float v1 = acc[mt][nt][hf * 2 + 1];
                if (kind == 0) {
                    size_t ob = (size_t)c_ao[lvl] + (size_t)(p0 + r) * 256 + oc;
                    float2 st = {v0 + __ldg(&bias[oc]), v1 + __ldg(&bias[oc + 1])};
                    *(float2*)&outp[ob] = st;
                } else if (oc < OC) {
                    long long unit =
                        (long long)sn[r] * TP + c_lb[lvl] + syy[r] * W + sxx[r];
                    v0 += __ldg(&bias[oc]);
                    v1 += __ldg(&bias[oc + 1]);
                    if (path == 0) {
                        outp[unit * 80 + oc] = v0;
                        outp[unit * 80 + oc + 1] = v1;
                    } else {
                        if (c_relu[oc]) v0 = fmaxf(v0, 0.f);
                        if (c_relu[oc + 1]) v1 = fmaxf(v1, 0.f);
                        outp[c_base[oc] + unit * c_ctot[oc] + c_ch[oc]] = v0;
                        outp[c_base[oc + 1] + unit * c_ctot[oc + 1] + c_ch[oc + 1]] = v1;
                    }
                }
            }
        }
    }
}

// ---------------------------------------------------------------------------
// GroupNorm, both paths per launch. gn_reduce grid 640, gn_apply grid (x,2).
// ---------------------------------------------------------------------------
__global__ void gn_reduce(const float* __restrict__ y0, const float* __restrict__ y1) {
    int bid = blockIdx.x;
    int pathv = bid >= 320 ? 1 : 0;
    int b2 = bid - pathv * 320;
    int l = b2 >> 6;
    int ng = b2 & 63;
    int n = ng >> 5, gr = ng & 31;
    int HW = c_HWs[l];
    const float* y = pathv ? y1 : y0;
    const float* base =
        y + c_ao[l] + (size_t)n * HW * 256 + gr * 8 + (threadIdx.x & 1) * 4;
    int tid = threadIdx.x;
    float s = 0.f, sq = 0.f;
    for (int p = tid >> 1; p < HW; p += 128) {
        float4 v = *(const float4*)&base[(size_t)p * 256];
        s += v.x + v.y + v.z + v.w;
        sq += v.x * v.x + v.y * v.y + v.z * v.z + v.w * v.w;
    }
    __shared__ float ss[256], ssq[256];
    ss[tid] = s; ssq[tid] = sq;
    __syncthreads();
    for (int off = 128; off > 0; off >>= 1) {
        if (tid < off) { ss[tid] += ss[tid + off]; ssq[tid] += ssq[tid + off]; }
        __syncthreads();
    }
    if (tid == 0) {
        float M = 8.f * HW;
        float mu = ss[0] / M;
        float var = ssq[0] / M - mu * mu;
        g_mean[bid] = mu;
        g_inv[bid] = rsqrtf(var + 1e-5f);
    }
}

__global__ void gn_apply(const float* __restrict__ y0, const float* __restrict__ y1,
                         __half* __restrict__ d0, __half* __restrict__ d1,
                         const float* __restrict__ gm0, const float* __restrict__ gm1,
                         const float* __restrict__ bt0, const float* __restrict__ bt1) {
    int idx = blockIdx.x * blockDim.x + threadIdx.x;
    if (idx >= TOTE / 4) return;
    int pathv = blockIdx.y;
    const float* y = pathv ? y1 : y0;
    __half* act = pathv ? d1 : d0;
    const float* gamma = pathv ? gm1 : gm0;
    const float* beta = pathv ? bt1 : bt0;
    int e = idx * 4;
    int l = (e >= c_ao[1]) + (e >= c_ao[2]) + (e >= c_ao[3]) + (e >= c_ao[4]);
    int c = e & 255;
    int pl = (e - c_ao[l]) >> 8;
    int n = pl >= c_HWs[l] ? 1 : 0;
    int ng = pathv * 320 + l * 64 + n * 32 + (c >> 3);
    float mu = g_mean[ng], iv = g_inv[ng];
    float4 v = *(const float4*)&y[e];
    float4 gmv = *(const float4*)&gamma[c];
    float4 btv = *(const float4*)&beta[c];
    __half2 h0 = __floats2half2_rn(fmaxf((v.x - mu) * iv * gmv.x + btv.x, 0.f),
                                   fmaxf((v.y - mu) * iv * gmv.y + btv.y, 0.f));
    __half2 h1 = __floats2half2_rn(fmaxf((v.z - mu) * iv * gmv.z + btv.z, 0.f),
                                   fmaxf((v.w - mu) * iv * gmv.w + btv.w, 0.f));
    uint2 st = {*(uint32_t*)&h0, *(uint32_t*)&h1};
    *(uint2*)&act[e] = st;
}

// ---------------------------------------------------------------------------
// Host orchestration
// ---------------------------------------------------------------------------
extern "C" void kernel_launch(void* const* d_in, const int* in_sizes, int n_in,
                              void* d_out, int out_size) {
    const float* feats[5];
    for (int i = 0; i < 5; i++) feats[i] = (const float*)d_in[i];
    const float* cls_conv_w = (const float*)d_in[5];
    const float* cls_conv_b = (const float*)d_in[6];
    const float* cls_gn_w = (const float*)d_in[7];
    const float* cls_gn_b = (const float*)d_in[8];
    const float* cls_out_w = (const float*)d_in[9];
    const float* cls_out_b = (const float*)d_in[10];
    const float* reg_conv_w = (const float*)d_in[11];
    const float* reg_conv_b = (const float*)d_in[12];
    const float* reg_gn_w = (const float*)d_in[13];
    const float* reg_gn_b = (const float*)d_in[14];
    float* out = (float*)d_out;

    __half *xh, *actA, *actB, *actC, *actD, *wtc, *wtr, *wtco, *wtro;
    float *ybuf, *ybuf2, *regw, *regb;
    cudaGetSymbolAddress((void**)&xh, g_xh);
    cudaGetSymbolAddress((void**)&actA, g_actA);
    cudaGetSymbolAddress((void**)&actB, g_actB);
    cudaGetSymbolAddress((void**)&actC, g_actC);
    cudaGetSymbolAddress((void**)&actD, g_actD);
    cudaGetSymbolAddress((void**)&ybuf, g_y);
    cudaGetSymbolAddress((void**)&ybuf2, g_y2);
    cudaGetSymbolAddress((void**)&regw, g_regw);
    cudaGetSymbolAddress((void**)&regb, g_regb);
    cudaGetSymbolAddress((void**)&wtc, g_wt_cls);
    cudaGetSymbolAddress((void**)&wtr, g_wt_reg);
    cudaGetSymbolAddress((void**)&wtco, g_wtc_out);
    cudaGetSymbolAddress((void**)&wtro, g_wtr_out);

    cudaFuncSetAttribute(gemm16, cudaFuncAttributeMaxDynamicSharedMemorySize,
                         DYN_SMEM);

    pack_reg<<<(26 * 2304 + 255) / 256, 256>>>(
        (const float*)d_in[15], (const float*)d_in[16],
        (const float*)d_in[17], (const float*)d_in[18],
        (const float*)d_in[19], (const float*)d_in[20],
        (const float*)d_in[21], (const float*)d_in[22],
        (const float*)d_in[23], (const float*)d_in[24],
        (const float*)d_in[25], (const float*)d_in[26]);

    int wtN = 4 * 9 * 256 * 256;
    pack_wt<<<(wtN + 255) / 256, 256>>>(cls_conv_w, wtc);
    pack_wt<<<(wtN + 255) / 256, 256>>>(reg_conv_w, wtr);
    int hN = 2 * 9 * 128 * 256;
    pack_headw<<<(hN + 255) / 256, 256>>>(cls_out_w, wtco, 80);
    pack_headw<<<(hN + 255) / 256, 256>>>(regw, wtro, 26);

    to_nhwc_half<<<dim3(475, 8, 10), dim3(32, 32)>>>(feats[0], feats[1], feats[2],
                                                     feats[3], feats[4], xh);

    int gApplyX = (TOTE / 4 + 255) / 256;
    const __half* curc = xh;
    const __half* curr = xh;
    __half* cd[4] = {actA, actB, actA, actB};
    __half* rd[4] = {actC, actD, actC, actD};
    for (int s = 0; s < 4; s++) {
        gemm16<<<dim3(NTILES, 4), 256, DYN_SMEM>>>(
            curc, curr, wtc + (size_t)s * 589824, wtr + (size_t)s * 589824,
            cls_conv_b + s * 256, reg_conv_b + s * 256, ybuf, ybuf2, 72, 0);
        gn_reduce<<<640, 256>>>(ybuf, ybuf2);
        gn_apply<<<dim3(gApplyX, 2), 256>>>(ybuf, ybuf2, cd[s], rd[s],
                                            cls_gn_w + s * 256, reg_gn_w + s * 256,
                                            cls_gn_b + s * 256, reg_gn_b + s * 256);
        curc = cd[s];
        curr = rd[s];
    }
    // heads: by 0 = cls (reads actB), by 1 = reg (reads actD)
    gemm16<<<dim3(NTILES, 2), 256, DYN_SMEM>>>(actB, actD, wtco, wtro, cls_out_b,
                                               regb, out, out, 144, 1);
    (void)in_sizes; (void)n_in; (void)out_size;
}